// round 12
// baseline (speedup 1.0000x reference)
#include <cuda_runtime.h>
#include <math.h>
#include <stdint.h>

#define N_NODES 50000
#define N_EDGES 500000
#define EF (N_EDGES + N_NODES)  /* 550000 */
#define NB_SCAN 196             /* ceil(N_NODES/256) */

/* ------------------------------------------------------------------ */
/* scratch (static device memory; no runtime allocation allowed)       */
/* ------------------------------------------------------------------ */
__device__ float g_xl[N_NODES * 256];
__device__ float g_xr[N_NODES * 256];
__device__ float g_z1[N_NODES * 128];
__device__ float g_z2[N_NODES * 128];
__device__ float g_gi[N_NODES * 384];
__device__ float g_h [N_NODES * 128];
__device__ float g_logit[N_EDGES * 2];
__device__ int   g_deg[N_NODES];
__device__ int   g_cursor[N_NODES];
__device__ int   g_off[N_NODES + 1];
__device__ int   g_eidx[EF];
__device__ float g_easum[32];
__device__ float g_loop_ea1[256];
__device__ float g_loop_ea2[128];
__device__ int   g_bsum[256];
__device__ int   g_bexcl[256];

/* ------------------------------------------------------------------ */
__device__ __forceinline__ uint32_t f2tf(float f) {
    uint32_t u;
    asm("cvt.rna.tf32.f32 %0, %1;" : "=r"(u) : "f"(f));
    return u;
}

__device__ __forceinline__ void mma_tf32(float* c,
        uint32_t a0, uint32_t a1, uint32_t a2, uint32_t a3,
        uint32_t b0, uint32_t b1) {
    asm volatile(
        "mma.sync.aligned.m16n8k8.row.col.f32.tf32.tf32.f32 "
        "{%0,%1,%2,%3}, {%4,%5,%6,%7}, {%8,%9}, {%0,%1,%2,%3};"
        : "+f"(c[0]), "+f"(c[1]), "+f"(c[2]), "+f"(c[3])
        : "r"(a0), "r"(a1), "r"(a2), "r"(a3), "r"(b0), "r"(b1));
}

/* ------------------------------------------------------------------ */
/* init / edge_attr mean / loop edge features                          */
/* ------------------------------------------------------------------ */
__global__ void k_init() {
    int i = blockIdx.x * blockDim.x + threadIdx.x;
    if (i < N_NODES) { g_deg[i] = 0; g_cursor[i] = 0; }
    if (i < 32) g_easum[i] = 0.f;
}

__global__ void k_easum(const float* __restrict__ ea) {
    __shared__ float s[8][32];
    int d = threadIdx.x & 31;
    int r = threadIdx.x >> 5;
    int base = blockIdx.x * 1024;
    int end  = base + 1024; if (end > N_EDGES) end = N_EDGES;
    float acc = 0.f;
    for (int e = base + r; e < end; e += 8)
        acc += ea[(size_t)e * 32 + d];
    s[r][d] = acc;
    __syncthreads();
    if (r == 0) {
        float t = 0.f;
        #pragma unroll
        for (int i = 0; i < 8; i++) t += s[i][d];
        atomicAdd(&g_easum[d], t);
    }
}

__global__ void k_loopea(const float* __restrict__ We1, const float* __restrict__ We2) {
    int j = threadIdx.x;
    float inv = 1.f / (float)N_EDGES;
    if (j < 256) {
        float s = 0.f;
        for (int d = 0; d < 32; d++) s += g_easum[d] * inv * We1[d * 256 + j];
        g_loop_ea1[j] = s;
    }
    if (j < 128) {
        float s = 0.f;
        for (int d = 0; d < 32; d++) s += g_easum[d] * inv * We2[d * 128 + j];
        g_loop_ea2[j] = s;
    }
}

/* ------------------------------------------------------------------ */
/* CSR build                                                           */
/* ------------------------------------------------------------------ */
__global__ void k_deg(const int* __restrict__ ei) {
    int e = blockIdx.x * blockDim.x + threadIdx.x;
    if (e >= EF) return;
    int dst = (e < N_EDGES) ? ei[N_EDGES + e] : (e - N_EDGES);
    atomicAdd(&g_deg[dst], 1);
}

__global__ void k_blocksum() {
    __shared__ int s[256];
    int i = blockIdx.x * 256 + threadIdx.x;
    s[threadIdx.x] = (i < N_NODES) ? g_deg[i] : 0;
    __syncthreads();
    for (int o = 128; o > 0; o >>= 1) {
        if (threadIdx.x < o) s[threadIdx.x] += s[threadIdx.x + o];
        __syncthreads();
    }
    if (threadIdx.x == 0) g_bsum[blockIdx.x] = s[0];
}

__global__ void k_scanb() {
    __shared__ int s[256];
    int t = threadIdx.x;
    int v = (t < NB_SCAN) ? g_bsum[t] : 0;
    s[t] = v;
    __syncthreads();
    for (int d = 1; d < 256; d <<= 1) {
        int x = (t >= d) ? s[t - d] : 0;
        __syncthreads();
        s[t] += x;
        __syncthreads();
    }
    g_bexcl[t] = s[t] - v;
}

__global__ void k_scanfinal() {
    __shared__ int s[256];
    int t = threadIdx.x;
    int i = blockIdx.x * 256 + t;
    int v = (i < N_NODES) ? g_deg[i] : 0;
    s[t] = v;
    __syncthreads();
    for (int d = 1; d < 256; d <<= 1) {
        int x = (t >= d) ? s[t - d] : 0;
        __syncthreads();
        s[t] += x;
        __syncthreads();
    }
    if (i < N_NODES) g_off[i] = g_bexcl[blockIdx.x] + s[t] - v;
    if (i == 0) g_off[N_NODES] = EF;
}

__global__ void k_scatter(const int* __restrict__ ei) {
    int e = blockIdx.x * blockDim.x + threadIdx.x;
    if (e >= EF) return;
    int dst = (e < N_EDGES) ? ei[N_EDGES + e] : (e - N_EDGES);
    int pos = atomicAdd(&g_cursor[dst], 1);
    g_eidx[g_off[dst] + pos] = e;
}

/* ------------------------------------------------------------------ */
/* tiled SGEMM  C[M,Nc] = A[M,128] @ B + bias   (fp32)                 */
/* ------------------------------------------------------------------ */
template <bool TRANSB>
__global__ void __launch_bounds__(256) k_gemm(
        const float* __restrict__ A, const float* __restrict__ B,
        const float* __restrict__ bias, float* __restrict__ C,
        int M, int Nc) {
    __shared__ float As[128][36];
    __shared__ float Bs[32][132];
    int tid = threadIdx.x;
    int tx = tid & 15, ty = tid >> 4;
    int row0 = blockIdx.y * 128;
    int col0 = blockIdx.x * 128;
    int j0 = tx * 8;
    float acc[8][8];
    #pragma unroll
    for (int i = 0; i < 8; i++)
        #pragma unroll
        for (int j = 0; j < 8; j++) acc[i][j] = 0.f;

    for (int kc = 0; kc < 4; kc++) {
        #pragma unroll
        for (int t = 0; t < 4; t++) {
            int idx4 = tid + t * 256;
            int r = idx4 >> 3, kk4 = idx4 & 7;
            float4 v = make_float4(0.f, 0.f, 0.f, 0.f);
            if (row0 + r < M)
                v = *(const float4*)(A + (size_t)(row0 + r) * 128 + kc * 32 + kk4 * 4);
            *(float4*)&As[r][kk4 * 4] = v;
        }
        if (!TRANSB) {
            #pragma unroll
            for (int t = 0; t < 4; t++) {
                int idx4 = tid + t * 256;
                int k = idx4 >> 5, c4 = idx4 & 31;
                float4 v = *(const float4*)(B + (size_t)(kc * 32 + k) * Nc + col0 + c4 * 4);
                *(float4*)&Bs[k][c4 * 4] = v;
            }
        } else {
            #pragma unroll
            for (int t = 0; t < 4; t++) {
                int idx4 = tid + t * 256;
                int j = idx4 >> 3, k4 = idx4 & 7;
                float4 v = *(const float4*)(B + (size_t)(col0 + j) * 128 + kc * 32 + k4 * 4);
                Bs[k4 * 4 + 0][j] = v.x;
                Bs[k4 * 4 + 1][j] = v.y;
                Bs[k4 * 4 + 2][j] = v.z;
                Bs[k4 * 4 + 3][j] = v.w;
            }
        }
        __syncthreads();
        #pragma unroll 8
        for (int kk = 0; kk < 32; kk++) {
            float4 b0 = *(const float4*)&Bs[kk][j0];
            float4 b1 = *(const float4*)&Bs[kk][j0 + 4];
            #pragma unroll
            for (int i = 0; i < 8; i++) {
                float a = As[ty * 8 + i][kk];
                acc[i][0] += a * b0.x; acc[i][1] += a * b0.y;
                acc[i][2] += a * b0.z; acc[i][3] += a * b0.w;
                acc[i][4] += a * b1.x; acc[i][5] += a * b1.y;
                acc[i][6] += a * b1.z; acc[i][7] += a * b1.w;
            }
        }
        __syncthreads();
    }
    float4 bv0 = *(const float4*)(bias + col0 + j0);
    float4 bv1 = *(const float4*)(bias + col0 + j0 + 4);
    #pragma unroll
    for (int i = 0; i < 8; i++) {
        int r = row0 + ty * 8 + i;
        if (r < M) {
            float4 o0, o1;
            o0.x = acc[i][0] + bv0.x; o0.y = acc[i][1] + bv0.y;
            o0.z = acc[i][2] + bv0.z; o0.w = acc[i][3] + bv0.w;
            o1.x = acc[i][4] + bv1.x; o1.y = acc[i][5] + bv1.y;
            o1.z = acc[i][6] + bv1.z; o1.w = acc[i][7] + bv1.w;
            *(float4*)(C + (size_t)r * Nc + col0 + j0) = o0;
            *(float4*)(C + (size_t)r * Nc + col0 + j0 + 4) = o1;
        }
    }
}

/* ------------------------------------------------------------------ */
/* GATv2 layer-1 logits, HEAD-SPLIT: warp per (8 edges, 1 head)        */
/* no lmax (softmax shift-invariance)                                  */
/* ------------------------------------------------------------------ */
__global__ void k_logit8h2(const int* __restrict__ ei, const float* __restrict__ edge_attr,
                           const float* __restrict__ We, const float* __restrict__ att) {
    int warp = (blockIdx.x * blockDim.x + threadIdx.x) >> 5;
    int e0 = (warp >> 1) * 8;
    int h = warp & 1;
    if (e0 >= N_EDGES) return;
    int lane = threadIdx.x & 31;
    int c0 = h * 128 + lane * 4;

    int srcs[8], dsts[8];
    float myea[8];
    #pragma unroll
    for (int j = 0; j < 8; j++) {
        int e = e0 + j;
        srcs[j] = ei[e];
        dsts[j] = ei[N_EDGES + e];
        myea[j] = edge_attr[(size_t)e * 32 + lane];
    }

    float ev[8][4];
    #pragma unroll
    for (int j = 0; j < 8; j++)
        #pragma unroll
        for (int q = 0; q < 4; q++) ev[j][q] = 0.f;

    #pragma unroll 4
    for (int d = 0; d < 32; d++) {
        float4 w = *(const float4*)(We + d * 256 + c0);
        #pragma unroll
        for (int j = 0; j < 8; j++) {
            float ad = __shfl_sync(0xffffffffu, myea[j], d);
            ev[j][0] += ad * w.x; ev[j][1] += ad * w.y;
            ev[j][2] += ad * w.z; ev[j][3] += ad * w.w;
        }
    }

    float4 at = *(const float4*)(att + c0);

    #pragma unroll
    for (int j = 0; j < 8; j++) {
        float4 a = *(const float4*)(g_xl + (size_t)srcs[j] * 256 + c0);
        float4 b = *(const float4*)(g_xr + (size_t)dsts[j] * 256 + c0);
        float s = 0.f, m;
        m = a.x + b.x + ev[j][0]; m = (m > 0.f) ? m : 0.2f * m; s += m * at.x;
        m = a.y + b.y + ev[j][1]; m = (m > 0.f) ? m : 0.2f * m; s += m * at.y;
        m = a.z + b.z + ev[j][2]; m = (m > 0.f) ? m : 0.2f * m; s += m * at.z;
        m = a.w + b.w + ev[j][3]; m = (m > 0.f) ? m : 0.2f * m; s += m * at.w;
        #pragma unroll
        for (int o = 16; o > 0; o >>= 1) s += __shfl_xor_sync(0xffffffffu, s, o);
        if (lane == 0)
            g_logit[(size_t)(e0 + j) * 2 + h] = s;
    }
}

/* layer-2 logits (H=1): warp per 8 edges, no lmax */
__global__ void k_logit8_l2(const int* __restrict__ ei, const float* __restrict__ edge_attr,
                            const float* __restrict__ We, const float* __restrict__ att) {
    int warp = (blockIdx.x * blockDim.x + threadIdx.x) >> 5;
    int e0 = warp * 8;
    if (e0 >= N_EDGES) return;
    int lane = threadIdx.x & 31;
    int c0 = lane * 4;

    int srcs[8], dsts[8];
    float myea[8];
    #pragma unroll
    for (int j = 0; j < 8; j++) {
        int e = e0 + j;
        srcs[j] = ei[e];
        dsts[j] = ei[N_EDGES + e];
        myea[j] = edge_attr[(size_t)e * 32 + lane];
    }

    float ev[8][4];
    #pragma unroll
    for (int j = 0; j < 8; j++)
        #pragma unroll
        for (int q = 0; q < 4; q++) ev[j][q] = 0.f;

    #pragma unroll 4
    for (int d = 0; d < 32; d++) {
        float4 w = *(const float4*)(We + d * 128 + c0);
        #pragma unroll
        for (int j = 0; j < 8; j++) {
            float ad = __shfl_sync(0xffffffffu, myea[j], d);
            ev[j][0] += ad * w.x; ev[j][1] += ad * w.y;
            ev[j][2] += ad * w.z; ev[j][3] += ad * w.w;
        }
    }

    float4 at = *(const float4*)(att + c0);

    #pragma unroll
    for (int j = 0; j < 8; j++) {
        float4 a = *(const float4*)(g_xl + (size_t)srcs[j] * 128 + c0);
        float4 b = *(const float4*)(g_xr + (size_t)dsts[j] * 128 + c0);
        float s = 0.f, m;
        m = a.x + b.x + ev[j][0]; m = (m > 0.f) ? m : 0.2f * m; s += m * at.x;
        m = a.y + b.y + ev[j][1]; m = (m > 0.f) ? m : 0.2f * m; s += m * at.y;
        m = a.z + b.z + ev[j][2]; m = (m > 0.f) ? m : 0.2f * m; s += m * at.z;
        m = a.w + b.w + ev[j][3]; m = (m > 0.f) ? m : 0.2f * m; s += m * at.w;
        #pragma unroll
        for (int o = 16; o > 0; o >>= 1) s += __shfl_xor_sync(0xffffffffu, s, o);
        if (lane == 0)
            g_logit[e0 + j] = s;
    }
}

/* ------------------------------------------------------------------ */
/* aggregation, fused softmax (no lmax) + inline self-loop logit       */
/* warp per dst node, CSR                                              */
/* ------------------------------------------------------------------ */
template <int H>
__global__ void k_agg(const int* __restrict__ ei, const float* __restrict__ bias,
                      const float* __restrict__ loop_ea, const float* __restrict__ att,
                      float* __restrict__ z) {
    const int HC = H * 128;
    const int CPL = HC / 32;
    int n = (blockIdx.x * blockDim.x + threadIdx.x) >> 5;
    if (n >= N_NODES) return;
    int lane = threadIdx.x & 31;
    int c0 = lane * CPL;
    int h = (H == 2) ? (lane >> 4) : 0;
    float sum_p = 0.f;
    float acc[8];
    #pragma unroll
    for (int q = 0; q < CPL; q++) acc[q] = 0.f;
    int b0 = g_off[n], b1 = g_off[n + 1];
    for (int idx = b0; idx < b1; idx++) {
        int e = g_eidx[idx];
        float p;
        int src;
        if (e < N_EDGES) {
            src = ei[e];
            p = __expf(g_logit[(size_t)e * H + h]);
            const float4* xp = (const float4*)(g_xl + (size_t)src * HC + c0);
            #pragma unroll
            for (int q4 = 0; q4 < CPL / 4; q4++) {
                float4 v = xp[q4];
                acc[q4 * 4 + 0] += p * v.x;
                acc[q4 * 4 + 1] += p * v.y;
                acc[q4 * 4 + 2] += p * v.z;
                acc[q4 * 4 + 3] += p * v.w;
            }
        } else {
            /* self loop: compute logit inline from xl[n]+xr[n]+loop_ea */
            const float4* xlp = (const float4*)(g_xl + (size_t)n * HC + c0);
            const float4* xrp = (const float4*)(g_xr + (size_t)n * HC + c0);
            const float4* lp  = (const float4*)(loop_ea + c0);
            const float4* ap  = (const float4*)(att + c0);
            float s = 0.f;
            float4 xlv[2];
            #pragma unroll
            for (int q4 = 0; q4 < CPL / 4; q4++) {
                float4 a = xlp[q4];
                xlv[q4] = a;
                float4 b = xrp[q4], e4 = lp[q4], at = ap[q4];
                float m;
                m = a.x + b.x + e4.x; m = (m > 0.f) ? m : 0.2f * m; s += m * at.x;
                m = a.y + b.y + e4.y; m = (m > 0.f) ? m : 0.2f * m; s += m * at.y;
                m = a.z + b.z + e4.z; m = (m > 0.f) ? m : 0.2f * m; s += m * at.z;
                m = a.w + b.w + e4.w; m = (m > 0.f) ? m : 0.2f * m; s += m * at.w;
            }
            if (H == 2) {
                /* reduce within each 16-lane half (one head each) */
                #pragma unroll
                for (int o = 8; o > 0; o >>= 1) s += __shfl_xor_sync(0xffffffffu, s, o);
            } else {
                #pragma unroll
                for (int o = 16; o > 0; o >>= 1) s += __shfl_xor_sync(0xffffffffu, s, o);
            }
            p = __expf(s);
            #pragma unroll
            for (int q4 = 0; q4 < CPL / 4; q4++) {
                acc[q4 * 4 + 0] += p * xlv[q4].x;
                acc[q4 * 4 + 1] += p * xlv[q4].y;
                acc[q4 * 4 + 2] += p * xlv[q4].z;
                acc[q4 * 4 + 3] += p * xlv[q4].w;
            }
        }
        sum_p += p;
    }
    float inv = 1.f / sum_p;
    #pragma unroll
    for (int q = 0; q < CPL; q++) acc[q] *= inv;
    if (H == 2) {
        #pragma unroll
        for (int q = 0; q < 8; q++)
            acc[q] = 0.5f * (acc[q] + __shfl_xor_sync(0xffffffffu, acc[q], 16));
        if (lane < 16) {
            int c = lane * 8;
            float4 o0, o1;
            float v;
            v = acc[0] + bias[c + 0]; o0.x = (v > 0.f) ? v : expm1f(v);
            v = acc[1] + bias[c + 1]; o0.y = (v > 0.f) ? v : expm1f(v);
            v = acc[2] + bias[c + 2]; o0.z = (v > 0.f) ? v : expm1f(v);
            v = acc[3] + bias[c + 3]; o0.w = (v > 0.f) ? v : expm1f(v);
            v = acc[4] + bias[c + 4]; o1.x = (v > 0.f) ? v : expm1f(v);
            v = acc[5] + bias[c + 5]; o1.y = (v > 0.f) ? v : expm1f(v);
            v = acc[6] + bias[c + 6]; o1.z = (v > 0.f) ? v : expm1f(v);
            v = acc[7] + bias[c + 7]; o1.w = (v > 0.f) ? v : expm1f(v);
            *(float4*)(z + (size_t)n * 128 + c) = o0;
            *(float4*)(z + (size_t)n * 128 + c + 4) = o1;
        }
    } else {
        int c = lane * 4;
        float4 o;
        float v;
        v = acc[0] + bias[c + 0]; o.x = (v > 0.f) ? v : expm1f(v);
        v = acc[1] + bias[c + 1]; o.y = (v > 0.f) ? v : expm1f(v);
        v = acc[2] + bias[c + 2]; o.z = (v > 0.f) ? v : expm1f(v);
        v = acc[3] + bias[c + 3]; o.w = (v > 0.f) ? v : expm1f(v);
        *(float4*)(z + (size_t)n * 128 + c) = o;
    }
}

/* ------------------------------------------------------------------ */
/* GRU (h_prev = 0): h = (1-u)*g                                       */
/* ------------------------------------------------------------------ */
__global__ void k_gru(const float* __restrict__ b_hh) {
    int i = blockIdx.x * blockDim.x + threadIdx.x;
    if (i >= N_NODES * 128) return;
    int n = i >> 7;
    int c = i & 127;
    const float* gi = g_gi + (size_t)n * 384;
    float r = 1.f / (1.f + __expf(-(gi[c] + b_hh[c])));
    float u = 1.f / (1.f + __expf(-(gi[128 + c] + b_hh[128 + c])));
    float g = tanhf(gi[256 + c] + r * b_hh[256 + c]);
    g_h[i] = (1.f - u) * g;
}

/* ------------------------------------------------------------------ */
/* fused edge classifier, tf32 tensor cores                            */
/* ------------------------------------------------------------------ */
#define CLS_SMEM_BYTES 103936

__global__ void __launch_bounds__(256) k_cls(
        const int* __restrict__ ei, const float* __restrict__ edge_attr,
        const float* __restrict__ Wc1, const float* __restrict__ bc1,
        const float* __restrict__ Wc2, const float* __restrict__ bc2,
        const float* __restrict__ Wc3, const float* __restrict__ bc3,
        float* __restrict__ out) {
    extern __shared__ char smem[];
    int*      s_src = (int*)smem;
    int*      s_dst = (int*)(smem + 512);
    uint32_t* sAu   = (uint32_t*)(smem + 1024);    /* [128][36]  tf32 */
    uint32_t* sBu   = (uint32_t*)(smem + 19456);   /* [32][132]  tf32 */
    uint32_t* sh1u  = (uint32_t*)(smem + 36352);   /* [128][132] tf32 */
    float*    sh2   = (float*)(smem + 1024);       /* [128][68] fp32 overlay */

    int tid = threadIdx.x;
    int e0 = blockIdx.x * 128;
    {
        int ge = e0 + (tid & 127);
        if (ge >= N_EDGES) ge = N_EDGES - 1;
        if (tid < 128) s_src[tid] = ei[ge];
        else           s_dst[tid - 128] = ei[N_EDGES + ge];
    }
    __syncthreads();

    int lane = tid & 31, w = tid >> 5;
    int g = lane >> 2, tig = lane & 3;
    int r0 = w * 16 + g;

    float acc[16][4];
    #pragma unroll
    for (int t = 0; t < 16; t++)
        #pragma unroll
        for (int q = 0; q < 4; q++) acc[t][q] = 0.f;

    for (int kc = 0; kc < 9; kc++) {
        #pragma unroll
        for (int t = 0; t < 4; t++) {
            int idx4 = tid + t * 256;
            int row = idx4 >> 3, kk4 = idx4 & 7;
            int k0 = kc * 32 + kk4 * 4;
            float4 v;
            if (kc < 4)
                v = *(const float4*)(g_h + (size_t)s_src[row] * 128 + k0);
            else if (kc < 8)
                v = *(const float4*)(g_h + (size_t)s_dst[row] * 128 + (k0 - 128));
            else {
                int ge = e0 + row; if (ge >= N_EDGES) ge = N_EDGES - 1;
                v = *(const float4*)(edge_attr + (size_t)ge * 32 + (k0 - 256));
            }
            uint4 u = make_uint4(f2tf(v.x), f2tf(v.y), f2tf(v.z), f2tf(v.w));
            *(uint4*)(sAu + row * 36 + kk4 * 4) = u;
        }
        #pragma unroll
        for (int t = 0; t < 4; t++) {
            int idx4 = tid + t * 256;
            int k = idx4 >> 5, c4 = idx4 & 31;
            float4 v = *(const float4*)(Wc1 + (size_t)(kc * 32 + k) * 128 + c4 * 4);
            uint4 u = make_uint4(f2tf(v.x), f2tf(v.y), f2tf(v.z), f2tf(v.w));
            *(uint4*)(sBu + k * 132 + c4 * 4) = u;
        }
        __syncthreads();
        #pragma unroll
        for (int ks = 0; ks < 4; ks++) {
            int k0 = ks * 8;
            uint32_t a0 = sAu[r0 * 36 + k0 + tig];
            uint32_t a1 = sAu[(r0 + 8) * 36 + k0 + tig];
            uint32_t a2 = sAu[r0 * 36 + k0 + tig + 4];
            uint32_t a3 = sAu[(r0 + 8) * 36 + k0 + tig + 4];
            #pragma unroll
            for (int t = 0; t < 16; t++) {
                uint32_t b0 = sBu[(k0 + tig) * 132 + t * 8 + g];
                uint32_t b1 = sBu[(k0 + tig + 4) * 132 + t * 8 + g];
                mma_tf32(acc[t], a0, a1, a2, a3, b0, b1);
            }
        }
        __syncthreads();
    }
    #pragma unroll
    for (int t = 0; t < 16; t++) {
        int c = t * 8 + tig * 2;
        float bb0 = bc1[c], bb1 = bc1[c + 1];
        sh1u[r0 * 132 + c]           = f2tf(fmaxf(acc[t][0] + bb0, 0.f));
        sh1u[r0 * 132 + c + 1]       = f2tf(fmaxf(acc[t][1] + bb1, 0.f));
        sh1u[(r0 + 8) * 132 + c]     = f2tf(fmaxf(acc[t][2] + bb0, 0.f));
        sh1u[(r0 + 8) * 132 + c + 1] = f2tf(fmaxf(acc[t][3] + bb1, 0.f));
    }
    __syncthreads();

    float acc2[8][4];
    #pragma unroll
    for (int t = 0; t < 8; t++)
        #pragma unroll
        for (int q = 0; q < 4; q++) acc2[t][q] = 0.f;

    for (int kc = 0; kc < 4; kc++) {
        #pragma unroll
        for (int t = 0; t < 2; t++) {
            int idx4 = tid + t * 256;
            int k = idx4 >> 4, c4 = idx4 & 15;
            float4 v = *(const float4*)(Wc2 + (size_t)(kc * 32 + k) * 64 + c4 * 4);
            uint4 u = make_uint4(f2tf(v.x), f2tf(v.y), f2tf(v.z), f2tf(v.w));
            *(uint4*)(sBu + k * 132 + c4 * 4) = u;
        }
        __syncthreads();
        #pragma unroll
        for (int ks = 0; ks < 4; ks++) {
            int kk = kc * 32 + ks * 8;
            uint32_t a0 = sh1u[r0 * 132 + kk + tig];
            uint32_t a1 = sh1u[(r0 + 8) * 132 + kk + tig];
            uint32_t a2 = sh1u[r0 * 132 + kk + tig + 4];
            uint32_t a3 = sh1u[(r0 + 8) * 132 + kk + tig + 4];
            #pragma unroll
            for (int t = 0; t < 8; t++) {
                uint32_t b0 = sBu[(ks * 8 + tig) * 132 + t * 8 + g];
                uint32_t b1 = sBu[(ks * 8 + tig + 4) * 132 + t * 8 + g];
                mma_tf32(acc2[t], a0, a1, a2, a3, b0, b1);
            }
        }
        __syncthreads();
    }
    #pragma unroll
    for (int t = 0; t < 8; t++) {
        int c = t * 8 + tig * 2;
        float bb0 = bc2[c], bb1 = bc2[c + 1];
        sh2[r0 * 68 + c]           = fmaxf(acc2[t][0] + bb0, 0.f);
        sh2[r0 * 68 + c + 1]       = fmaxf(acc2[t][1] + bb1, 0.f);
        sh2[(r0 + 8) * 68 + c]     = fmaxf(acc2[t][2] + bb0, 0.f);
        sh2[(r0 + 8) * 68 + c + 1] = fmaxf(acc2[t][3] + bb1, 0.f);
    }
    __syncthreads();

    {
        int e = tid >> 1;
        int o = tid & 1;
        float s = bc3[o];
        const float* hr = sh2 + e * 68;
        #pragma unroll 8
        for (int k = 0; k < 64; k++) s += hr[k] * Wc3[k * 2 + o];
        int ge = e0 + e;
        if (ge < N_EDGES) out[(size_t)ge * 2 + o] = s;
    }
}

/* ------------------------------------------------------------------ */
/* launch: dual-stream overlap                                         */
/* ------------------------------------------------------------------ */
extern "C" void kernel_launch(void* const* d_in, const int* in_sizes, int n_in,
                              void* d_out, int out_size) {
    (void)in_sizes; (void)n_in; (void)out_size;
    const float* x     = (const float*)d_in[0];
    const int*   ei    = (const int*)d_in[1];
    const float* ea    = (const float*)d_in[2];
    /* d_in[3] global_ids unused */
    const float* Wl1 = (const float*)d_in[4];
    const float* bl1 = (const float*)d_in[5];
    const float* Wr1 = (const float*)d_in[6];
    const float* br1 = (const float*)d_in[7];
    const float* We1 = (const float*)d_in[8];
    const float* att1 = (const float*)d_in[9];
    const float* bias1 = (const float*)d_in[10];
    const float* Wl2 = (const float*)d_in[11];
    const float* bl2 = (const float*)d_in[12];
    const float* Wr2 = (const float*)d_in[13];
    const float* br2 = (const float*)d_in[14];
    const float* We2 = (const float*)d_in[15];
    const float* att2 = (const float*)d_in[16];
    const float* bias2 = (const float*)d_in[17];
    const float* W_ih = (const float*)d_in[18];
    /* d_in[19] W_hh unused: h_prev == 0 */
    const float* b_ih = (const float*)d_in[20];
    const float* b_hh = (const float*)d_in[21];
    const float* Wc1 = (const float*)d_in[22];
    const float* bc1 = (const float*)d_in[23];
    const float* Wc2 = (const float*)d_in[24];
    const float* bc2 = (const float*)d_in[25];
    const float* Wc3 = (const float*)d_in[26];
    const float* bc3 = (const float*)d_in[27];
    float* out = (float*)d_out;

    float *p_xl, *p_xr, *p_z1, *p_z2, *p_gi, *p_lea1, *p_lea2;
    cudaGetSymbolAddress((void**)&p_xl, g_xl);
    cudaGetSymbolAddress((void**)&p_xr, g_xr);
    cudaGetSymbolAddress((void**)&p_z1, g_z1);
    cudaGetSymbolAddress((void**)&p_z2, g_z2);
    cudaGetSymbolAddress((void**)&p_gi, g_gi);
    cudaGetSymbolAddress((void**)&p_lea1, g_loop_ea1);
    cudaGetSymbolAddress((void**)&p_lea2, g_loop_ea2);

    /* one-time setup (first call is the uncaptured correctness run) */
    static int setup_done = 0;
    static cudaStream_t s2;
    static cudaEvent_t ev0, evCSR, evAgg1, evX2;
    if (!setup_done) {
        cudaFuncSetAttribute(k_cls, cudaFuncAttributeMaxDynamicSharedMemorySize,
                             CLS_SMEM_BYTES);
        cudaStreamCreateWithFlags(&s2, cudaStreamNonBlocking);
        cudaEventCreateWithFlags(&ev0,   cudaEventDisableTiming);
        cudaEventCreateWithFlags(&evCSR, cudaEventDisableTiming);
        cudaEventCreateWithFlags(&evAgg1, cudaEventDisableTiming);
        cudaEventCreateWithFlags(&evX2,  cudaEventDisableTiming);
        setup_done = 1;
    }

    dim3 tb(256);
    int gy = (N_NODES + 127) / 128;
    int logit_blocks_l1 = (N_EDGES / 8 * 2 + 7) / 8;
    int logit_blocks_l2 = (N_EDGES / 8 + 7) / 8;

    /* main: init, then the layer-1 GEMM+logit chain (logit8h2 = 4th launch) */
    k_init<<<(N_NODES + 255) / 256, 256>>>();
    cudaEventRecord(ev0, 0);
    k_gemm<false><<<dim3(2, gy), tb>>>(x, Wl1, bl1, p_xl, N_NODES, 256);
    k_gemm<false><<<dim3(2, gy), tb>>>(x, Wr1, br1, p_xr, N_NODES, 256);
    k_logit8h2<<<logit_blocks_l1, 256>>>(ei, ea, We1, att1);

    /* side stream: easum/loopea + CSR build, forked after k_init */
    cudaStreamWaitEvent(s2, ev0, 0);
    k_easum<<<(N_EDGES + 1023) / 1024, 256, 0, s2>>>(ea);
    k_loopea<<<1, 256, 0, s2>>>(We1, We2);
    k_deg<<<(EF + 255) / 256, 256, 0, s2>>>(ei);
    k_blocksum<<<NB_SCAN, 256, 0, s2>>>();
    k_scanb<<<1, 256, 0, s2>>>();
    k_scanfinal<<<NB_SCAN, 256, 0, s2>>>();
    k_scatter<<<(EF + 255) / 256, 256, 0, s2>>>(ei);
    cudaEventRecord(evCSR, s2);

    /* main: agg needs CSR + loopea (both covered by evCSR) */
    cudaStreamWaitEvent(0, evCSR, 0);
    k_agg<2><<<(N_NODES + 7) / 8, 256>>>(ei, bias1, p_lea1, att1, p_z1);
    cudaEventRecord(evAgg1, 0);

    /* layer 2: xl2 on main, xr2 concurrent on s2 */
    cudaStreamWaitEvent(s2, evAgg1, 0);
    k_gemm<false><<<dim3(1, gy), tb, 0, s2>>>(p_z1, Wr2, br2, p_xr, N_NODES, 128);
    cudaEventRecord(evX2, s2);
    k_gemm<false><<<dim3(1, gy), tb>>>(p_z1, Wl2, bl2, p_xl, N_NODES, 128);
    cudaStreamWaitEvent(0, evX2, 0);
    k_logit8_l2<<<logit_blocks_l2, 256>>>(ei, ea, We2, att2);
    k_agg<1><<<(N_NODES + 7) / 8, 256>>>(ei, bias2, p_lea2, att2, p_z2);

    /* GRU (h_prev = 0) */
    k_gemm<true><<<dim3(3, gy), tb>>>(p_z2, W_ih, b_ih, p_gi, N_NODES, 384);
    k_gru<<<(N_NODES * 128 + 255) / 256, 256>>>(b_hh);

    /* edge classifier (tf32 tensor cores) */
    k_cls<<<(N_EDGES + 127) / 128, 256, CLS_SMEM_BYTES>>>(
        ei, ea, Wc1, bc1, Wc2, bc2, Wc3, bc3, out);
}

// round 13
// speedup vs baseline: 1.0208x; 1.0208x over previous
#include <cuda_runtime.h>
#include <math.h>
#include <stdint.h>

#define N_NODES 50000
#define N_EDGES 500000
#define EF (N_EDGES + N_NODES)  /* 550000 */
#define NB_SCAN 196             /* ceil(N_NODES/256) */

/* ------------------------------------------------------------------ */
/* scratch (static device memory; no runtime allocation allowed)       */
/* ------------------------------------------------------------------ */
__device__ float g_xl[N_NODES * 256];
__device__ float g_xr[N_NODES * 256];
__device__ float g_z1[N_NODES * 128];
__device__ float g_z2[N_NODES * 128];
__device__ float g_gi[N_NODES * 384];
__device__ float g_h [N_NODES * 128];
__device__ float g_logit[EF * 2];
__device__ int   g_deg[N_NODES];
__device__ int   g_cursor[N_NODES];
__device__ int   g_off[N_NODES + 1];
__device__ int   g_eidx[EF];
__device__ float g_easum[32];
__device__ float g_loop_ea1[256];
__device__ float g_loop_ea2[128];
__device__ int   g_bsum[256];
__device__ int   g_bexcl[256];

/* ------------------------------------------------------------------ */
__device__ __forceinline__ uint32_t f2tf(float f) {
    uint32_t u;
    asm("cvt.rna.tf32.f32 %0, %1;" : "=r"(u) : "f"(f));
    return u;
}

__device__ __forceinline__ void mma_tf32(float* c,
        uint32_t a0, uint32_t a1, uint32_t a2, uint32_t a3,
        uint32_t b0, uint32_t b1) {
    asm volatile(
        "mma.sync.aligned.m16n8k8.row.col.f32.tf32.tf32.f32 "
        "{%0,%1,%2,%3}, {%4,%5,%6,%7}, {%8,%9}, {%0,%1,%2,%3};"
        : "+f"(c[0]), "+f"(c[1]), "+f"(c[2]), "+f"(c[3])
        : "r"(a0), "r"(a1), "r"(a2), "r"(a3), "r"(b0), "r"(b1));
}

/* ------------------------------------------------------------------ */
/* init / edge_attr mean / loop edge features                          */
/* ------------------------------------------------------------------ */
__global__ void k_init() {
    int i = blockIdx.x * blockDim.x + threadIdx.x;
    if (i < N_NODES) { g_deg[i] = 0; g_cursor[i] = 0; }
    if (i < 32) g_easum[i] = 0.f;
}

__global__ void k_easum(const float* __restrict__ ea) {
    __shared__ float s[8][32];
    int d = threadIdx.x & 31;
    int r = threadIdx.x >> 5;
    int base = blockIdx.x * 1024;
    int end  = base + 1024; if (end > N_EDGES) end = N_EDGES;
    float acc = 0.f;
    for (int e = base + r; e < end; e += 8)
        acc += ea[(size_t)e * 32 + d];
    s[r][d] = acc;
    __syncthreads();
    if (r == 0) {
        float t = 0.f;
        #pragma unroll
        for (int i = 0; i < 8; i++) t += s[i][d];
        atomicAdd(&g_easum[d], t);
    }
}

__global__ void k_loopea(const float* __restrict__ We1, const float* __restrict__ We2) {
    int j = threadIdx.x;
    float inv = 1.f / (float)N_EDGES;
    if (j < 256) {
        float s = 0.f;
        for (int d = 0; d < 32; d++) s += g_easum[d] * inv * We1[d * 256 + j];
        g_loop_ea1[j] = s;
    }
    if (j < 128) {
        float s = 0.f;
        for (int d = 0; d < 32; d++) s += g_easum[d] * inv * We2[d * 128 + j];
        g_loop_ea2[j] = s;
    }
}

/* ------------------------------------------------------------------ */
/* CSR build                                                           */
/* ------------------------------------------------------------------ */
__global__ void k_deg(const int* __restrict__ ei) {
    int e = blockIdx.x * blockDim.x + threadIdx.x;
    if (e >= EF) return;
    int dst = (e < N_EDGES) ? ei[N_EDGES + e] : (e - N_EDGES);
    atomicAdd(&g_deg[dst], 1);
}

__global__ void k_blocksum() {
    __shared__ int s[256];
    int i = blockIdx.x * 256 + threadIdx.x;
    s[threadIdx.x] = (i < N_NODES) ? g_deg[i] : 0;
    __syncthreads();
    for (int o = 128; o > 0; o >>= 1) {
        if (threadIdx.x < o) s[threadIdx.x] += s[threadIdx.x + o];
        __syncthreads();
    }
    if (threadIdx.x == 0) g_bsum[blockIdx.x] = s[0];
}

__global__ void k_scanb() {
    __shared__ int s[256];
    int t = threadIdx.x;
    int v = (t < NB_SCAN) ? g_bsum[t] : 0;
    s[t] = v;
    __syncthreads();
    for (int d = 1; d < 256; d <<= 1) {
        int x = (t >= d) ? s[t - d] : 0;
        __syncthreads();
        s[t] += x;
        __syncthreads();
    }
    g_bexcl[t] = s[t] - v;
}

__global__ void k_scanfinal() {
    __shared__ int s[256];
    int t = threadIdx.x;
    int i = blockIdx.x * 256 + t;
    int v = (i < N_NODES) ? g_deg[i] : 0;
    s[t] = v;
    __syncthreads();
    for (int d = 1; d < 256; d <<= 1) {
        int x = (t >= d) ? s[t - d] : 0;
        __syncthreads();
        s[t] += x;
        __syncthreads();
    }
    if (i < N_NODES) g_off[i] = g_bexcl[blockIdx.x] + s[t] - v;
    if (i == 0) g_off[N_NODES] = EF;
}

__global__ void k_scatter(const int* __restrict__ ei) {
    int e = blockIdx.x * blockDim.x + threadIdx.x;
    if (e >= EF) return;
    int dst = (e < N_EDGES) ? ei[N_EDGES + e] : (e - N_EDGES);
    int pos = atomicAdd(&g_cursor[dst], 1);
    g_eidx[g_off[dst] + pos] = e;
}

/* ------------------------------------------------------------------ */
/* tiled SGEMM  C[M,Nc] = A[M,128] @ B + bias   (fp32)                 */
/* ------------------------------------------------------------------ */
template <bool TRANSB>
__global__ void __launch_bounds__(256) k_gemm(
        const float* __restrict__ A, const float* __restrict__ B,
        const float* __restrict__ bias, float* __restrict__ C,
        int M, int Nc) {
    __shared__ float As[128][36];
    __shared__ float Bs[32][132];
    int tid = threadIdx.x;
    int tx = tid & 15, ty = tid >> 4;
    int row0 = blockIdx.y * 128;
    int col0 = blockIdx.x * 128;
    int j0 = tx * 8;
    float acc[8][8];
    #pragma unroll
    for (int i = 0; i < 8; i++)
        #pragma unroll
        for (int j = 0; j < 8; j++) acc[i][j] = 0.f;

    for (int kc = 0; kc < 4; kc++) {
        #pragma unroll
        for (int t = 0; t < 4; t++) {
            int idx4 = tid + t * 256;
            int r = idx4 >> 3, kk4 = idx4 & 7;
            float4 v = make_float4(0.f, 0.f, 0.f, 0.f);
            if (row0 + r < M)
                v = *(const float4*)(A + (size_t)(row0 + r) * 128 + kc * 32 + kk4 * 4);
            *(float4*)&As[r][kk4 * 4] = v;
        }
        if (!TRANSB) {
            #pragma unroll
            for (int t = 0; t < 4; t++) {
                int idx4 = tid + t * 256;
                int k = idx4 >> 5, c4 = idx4 & 31;
                float4 v = *(const float4*)(B + (size_t)(kc * 32 + k) * Nc + col0 + c4 * 4);
                *(float4*)&Bs[k][c4 * 4] = v;
            }
        } else {
            #pragma unroll
            for (int t = 0; t < 4; t++) {
                int idx4 = tid + t * 256;
                int j = idx4 >> 3, k4 = idx4 & 7;
                float4 v = *(const float4*)(B + (size_t)(col0 + j) * 128 + kc * 32 + k4 * 4);
                Bs[k4 * 4 + 0][j] = v.x;
                Bs[k4 * 4 + 1][j] = v.y;
                Bs[k4 * 4 + 2][j] = v.z;
                Bs[k4 * 4 + 3][j] = v.w;
            }
        }
        __syncthreads();
        #pragma unroll 8
        for (int kk = 0; kk < 32; kk++) {
            float4 b0 = *(const float4*)&Bs[kk][j0];
            float4 b1 = *(const float4*)&Bs[kk][j0 + 4];
            #pragma unroll
            for (int i = 0; i < 8; i++) {
                float a = As[ty * 8 + i][kk];
                acc[i][0] += a * b0.x; acc[i][1] += a * b0.y;
                acc[i][2] += a * b0.z; acc[i][3] += a * b0.w;
                acc[i][4] += a * b1.x; acc[i][5] += a * b1.y;
                acc[i][6] += a * b1.z; acc[i][7] += a * b1.w;
            }
        }
        __syncthreads();
    }
    float4 bv0 = *(const float4*)(bias + col0 + j0);
    float4 bv1 = *(const float4*)(bias + col0 + j0 + 4);
    #pragma unroll
    for (int i = 0; i < 8; i++) {
        int r = row0 + ty * 8 + i;
        if (r < M) {
            float4 o0, o1;
            o0.x = acc[i][0] + bv0.x; o0.y = acc[i][1] + bv0.y;
            o0.z = acc[i][2] + bv0.z; o0.w = acc[i][3] + bv0.w;
            o1.x = acc[i][4] + bv1.x; o1.y = acc[i][5] + bv1.y;
            o1.z = acc[i][6] + bv1.z; o1.w = acc[i][7] + bv1.w;
            *(float4*)(C + (size_t)r * Nc + col0 + j0) = o0;
            *(float4*)(C + (size_t)r * Nc + col0 + j0 + 4) = o1;
        }
    }
}

/* ------------------------------------------------------------------ */
/* GATv2 layer-1 logits, HEAD-SPLIT: warp per (8 edges, 1 head)        */
/* no lmax, no atomics                                                 */
/* ------------------------------------------------------------------ */
__global__ void k_logit8h2(const int* __restrict__ ei, const float* __restrict__ edge_attr,
                           const float* __restrict__ We, const float* __restrict__ att) {
    int warp = (blockIdx.x * blockDim.x + threadIdx.x) >> 5;
    int e0 = (warp >> 1) * 8;
    int h = warp & 1;
    if (e0 >= N_EDGES) return;
    int lane = threadIdx.x & 31;
    int c0 = h * 128 + lane * 4;

    int srcs[8], dsts[8];
    float myea[8];
    #pragma unroll
    for (int j = 0; j < 8; j++) {
        int e = e0 + j;
        srcs[j] = ei[e];
        dsts[j] = ei[N_EDGES + e];
        myea[j] = edge_attr[(size_t)e * 32 + lane];
    }
    (void)dsts;

    float ev[8][4];
    #pragma unroll
    for (int j = 0; j < 8; j++)
        #pragma unroll
        for (int q = 0; q < 4; q++) ev[j][q] = 0.f;

    #pragma unroll 4
    for (int d = 0; d < 32; d++) {
        float4 w = *(const float4*)(We + d * 256 + c0);
        #pragma unroll
        for (int j = 0; j < 8; j++) {
            float ad = __shfl_sync(0xffffffffu, myea[j], d);
            ev[j][0] += ad * w.x; ev[j][1] += ad * w.y;
            ev[j][2] += ad * w.z; ev[j][3] += ad * w.w;
        }
    }

    float4 at = *(const float4*)(att + c0);

    #pragma unroll
    for (int j = 0; j < 8; j++) {
        float4 a = *(const float4*)(g_xl + (size_t)srcs[j] * 256 + c0);
        float4 b = *(const float4*)(g_xr + (size_t)dsts[j] * 256 + c0);
        float s = 0.f, m;
        m = a.x + b.x + ev[j][0]; m = (m > 0.f) ? m : 0.2f * m; s += m * at.x;
        m = a.y + b.y + ev[j][1]; m = (m > 0.f) ? m : 0.2f * m; s += m * at.y;
        m = a.z + b.z + ev[j][2]; m = (m > 0.f) ? m : 0.2f * m; s += m * at.z;
        m = a.w + b.w + ev[j][3]; m = (m > 0.f) ? m : 0.2f * m; s += m * at.w;
        #pragma unroll
        for (int o = 16; o > 0; o >>= 1) s += __shfl_xor_sync(0xffffffffu, s, o);
        if (lane == 0)
            g_logit[(size_t)(e0 + j) * 2 + h] = s;
    }
}

/* layer-2 logits (H=1): warp per 8 edges, no lmax */
__global__ void k_logit8_l2(const int* __restrict__ ei, const float* __restrict__ edge_attr,
                            const float* __restrict__ We, const float* __restrict__ att) {
    int warp = (blockIdx.x * blockDim.x + threadIdx.x) >> 5;
    int e0 = warp * 8;
    if (e0 >= N_EDGES) return;
    int lane = threadIdx.x & 31;
    int c0 = lane * 4;

    int srcs[8], dsts[8];
    float myea[8];
    #pragma unroll
    for (int j = 0; j < 8; j++) {
        int e = e0 + j;
        srcs[j] = ei[e];
        dsts[j] = ei[N_EDGES + e];
        myea[j] = edge_attr[(size_t)e * 32 + lane];
    }
    (void)dsts;

    float ev[8][4];
    #pragma unroll
    for (int j = 0; j < 8; j++)
        #pragma unroll
        for (int q = 0; q < 4; q++) ev[j][q] = 0.f;

    #pragma unroll 4
    for (int d = 0; d < 32; d++) {
        float4 w = *(const float4*)(We + d * 128 + c0);
        #pragma unroll
        for (int j = 0; j < 8; j++) {
            float ad = __shfl_sync(0xffffffffu, myea[j], d);
            ev[j][0] += ad * w.x; ev[j][1] += ad * w.y;
            ev[j][2] += ad * w.z; ev[j][3] += ad * w.w;
        }
    }

    float4 at = *(const float4*)(att + c0);

    #pragma unroll
    for (int j = 0; j < 8; j++) {
        float4 a = *(const float4*)(g_xl + (size_t)srcs[j] * 128 + c0);
        float4 b = *(const float4*)(g_xr + (size_t)dsts[j] * 128 + c0);
        float s = 0.f, m;
        m = a.x + b.x + ev[j][0]; m = (m > 0.f) ? m : 0.2f * m; s += m * at.x;
        m = a.y + b.y + ev[j][1]; m = (m > 0.f) ? m : 0.2f * m; s += m * at.y;
        m = a.z + b.z + ev[j][2]; m = (m > 0.f) ? m : 0.2f * m; s += m * at.z;
        m = a.w + b.w + ev[j][3]; m = (m > 0.f) ? m : 0.2f * m; s += m * at.w;
        #pragma unroll
        for (int o = 16; o > 0; o >>= 1) s += __shfl_xor_sync(0xffffffffu, s, o);
        if (lane == 0)
            g_logit[e0 + j] = s;
    }
}

/* self-loop logits: warp per node, no lmax */
template <int H>
__global__ void k_logit_self(const float* __restrict__ att,
                             const float* __restrict__ loop_ea) {
    const int HC = H * 128;
    const int CPL = HC / 32;
    int n = (blockIdx.x * blockDim.x + threadIdx.x) >> 5;
    if (n >= N_NODES) return;
    int lane = threadIdx.x & 31;
    int c0 = lane * CPL;
    const float4* xlp = (const float4*)(g_xl + (size_t)n * HC + c0);
    const float4* xrp = (const float4*)(g_xr + (size_t)n * HC + c0);
    const float4* lp  = (const float4*)(loop_ea + c0);
    const float4* ap  = (const float4*)(att + c0);
    float s = 0.f;
    #pragma unroll
    for (int q4 = 0; q4 < CPL / 4; q4++) {
        float4 a = xlp[q4], b = xrp[q4], e = lp[q4], at = ap[q4];
        float m;
        m = a.x + b.x + e.x; m = (m > 0.f) ? m : 0.2f * m; s += m * at.x;
        m = a.y + b.y + e.y; m = (m > 0.f) ? m : 0.2f * m; s += m * at.y;
        m = a.z + b.z + e.z; m = (m > 0.f) ? m : 0.2f * m; s += m * at.z;
        m = a.w + b.w + e.w; m = (m > 0.f) ? m : 0.2f * m; s += m * at.w;
    }
    if (H == 2) {
        #pragma unroll
        for (int o = 8; o > 0; o >>= 1) s += __shfl_xor_sync(0xffffffffu, s, o);
        if ((lane & 15) == 0) {
            int h = lane >> 4;
            g_logit[(size_t)(N_EDGES + n) * 2 + h] = s;
        }
    } else {
        #pragma unroll
        for (int o = 16; o > 0; o >>= 1) s += __shfl_xor_sync(0xffffffffu, s, o);
        if (lane == 0)
            g_logit[N_EDGES + n] = s;
    }
}

/* ------------------------------------------------------------------ */
/* aggregation, fused softmax (no lmax): warp per dst node, CSR        */
/* ------------------------------------------------------------------ */
template <int H>
__global__ void k_agg(const int* __restrict__ ei, const float* __restrict__ bias,
                      float* __restrict__ z) {
    const int HC = H * 128;
    const int CPL = HC / 32;
    int n = (blockIdx.x * blockDim.x + threadIdx.x) >> 5;
    if (n >= N_NODES) return;
    int lane = threadIdx.x & 31;
    int c0 = lane * CPL;
    int h = (H == 2) ? (lane >> 4) : 0;
    float sum_p = 0.f;
    float acc[8];
    #pragma unroll
    for (int q = 0; q < CPL; q++) acc[q] = 0.f;
    int b0 = g_off[n], b1 = g_off[n + 1];
    for (int idx = b0; idx < b1; idx++) {
        int e = g_eidx[idx];
        int src = (e < N_EDGES) ? ei[e] : n;
        float p = __expf(g_logit[(size_t)e * H + h]);
        sum_p += p;
        const float4* xp = (const float4*)(g_xl + (size_t)src * HC + c0);
        #pragma unroll
        for (int q4 = 0; q4 < CPL / 4; q4++) {
            float4 v = xp[q4];
            acc[q4 * 4 + 0] += p * v.x;
            acc[q4 * 4 + 1] += p * v.y;
            acc[q4 * 4 + 2] += p * v.z;
            acc[q4 * 4 + 3] += p * v.w;
        }
    }
    float inv = 1.f / sum_p;
    #pragma unroll
    for (int q = 0; q < CPL; q++) acc[q] *= inv;
    if (H == 2) {
        #pragma unroll
        for (int q = 0; q < 8; q++)
            acc[q] = 0.5f * (acc[q] + __shfl_xor_sync(0xffffffffu, acc[q], 16));
        if (lane < 16) {
            int c = lane * 8;
            float4 o0, o1;
            float v;
            v = acc[0] + bias[c + 0]; o0.x = (v > 0.f) ? v : expm1f(v);
            v = acc[1] + bias[c + 1]; o0.y = (v > 0.f) ? v : expm1f(v);
            v = acc[2] + bias[c + 2]; o0.z = (v > 0.f) ? v : expm1f(v);
            v = acc[3] + bias[c + 3]; o0.w = (v > 0.f) ? v : expm1f(v);
            v = acc[4] + bias[c + 4]; o1.x = (v > 0.f) ? v : expm1f(v);
            v = acc[5] + bias[c + 5]; o1.y = (v > 0.f) ? v : expm1f(v);
            v = acc[6] + bias[c + 6]; o1.z = (v > 0.f) ? v : expm1f(v);
            v = acc[7] + bias[c + 7]; o1.w = (v > 0.f) ? v : expm1f(v);
            *(float4*)(z + (size_t)n * 128 + c) = o0;
            *(float4*)(z + (size_t)n * 128 + c + 4) = o1;
        }
    } else {
        int c = lane * 4;
        float4 o;
        float v;
        v = acc[0] + bias[c + 0]; o.x = (v > 0.f) ? v : expm1f(v);
        v = acc[1] + bias[c + 1]; o.y = (v > 0.f) ? v : expm1f(v);
        v = acc[2] + bias[c + 2]; o.z = (v > 0.f) ? v : expm1f(v);
        v = acc[3] + bias[c + 3]; o.w = (v > 0.f) ? v : expm1f(v);
        *(float4*)(z + (size_t)n * 128 + c) = o;
    }
}

/* ------------------------------------------------------------------ */
/* GRU (h_prev = 0): h = (1-u)*g                                       */
/* ------------------------------------------------------------------ */
__global__ void k_gru(const float* __restrict__ b_hh) {
    int i = blockIdx.x * blockDim.x + threadIdx.x;
    if (i >= N_NODES * 128) return;
    int n = i >> 7;
    int c = i & 127;
    const float* gi = g_gi + (size_t)n * 384;
    float r = 1.f / (1.f + __expf(-(gi[c] + b_hh[c])));
    float u = 1.f / (1.f + __expf(-(gi[128 + c] + b_hh[128 + c])));
    float g = tanhf(gi[256 + c] + r * b_hh[256 + c]);
    g_h[i] = (1.f - u) * g;
}

/* ------------------------------------------------------------------ */
/* fused edge classifier, tf32 tensor cores                            */
/* ------------------------------------------------------------------ */
#define CLS_SMEM_BYTES 103936

__global__ void __launch_bounds__(256) k_cls(
        const int* __restrict__ ei, const float* __restrict__ edge_attr,
        const float* __restrict__ Wc1, const float* __restrict__ bc1,
        const float* __restrict__ Wc2, const float* __restrict__ bc2,
        const float* __restrict__ Wc3, const float* __restrict__ bc3,
        float* __restrict__ out) {
    extern __shared__ char smem[];
    int*      s_src = (int*)smem;
    int*      s_dst = (int*)(smem + 512);
    uint32_t* sAu   = (uint32_t*)(smem + 1024);    /* [128][36]  tf32 */
    uint32_t* sBu   = (uint32_t*)(smem + 19456);   /* [32][132]  tf32 */
    uint32_t* sh1u  = (uint32_t*)(smem + 36352);   /* [128][132] tf32 */
    float*    sh2   = (float*)(smem + 1024);       /* [128][68] fp32 overlay */

    int tid = threadIdx.x;
    int e0 = blockIdx.x * 128;
    {
        int ge = e0 + (tid & 127);
        if (ge >= N_EDGES) ge = N_EDGES - 1;
        if (tid < 128) s_src[tid] = ei[ge];
        else           s_dst[tid - 128] = ei[N_EDGES + ge];
    }
    __syncthreads();

    int lane = tid & 31, w = tid >> 5;
    int g = lane >> 2, tig = lane & 3;
    int r0 = w * 16 + g;

    float acc[16][4];
    #pragma unroll
    for (int t = 0; t < 16; t++)
        #pragma unroll
        for (int q = 0; q < 4; q++) acc[t][q] = 0.f;

    for (int kc = 0; kc < 9; kc++) {
        #pragma unroll
        for (int t = 0; t < 4; t++) {
            int idx4 = tid + t * 256;
            int row = idx4 >> 3, kk4 = idx4 & 7;
            int k0 = kc * 32 + kk4 * 4;
            float4 v;
            if (kc < 4)
                v = *(const float4*)(g_h + (size_t)s_src[row] * 128 + k0);
            else if (kc < 8)
                v = *(const float4*)(g_h + (size_t)s_dst[row] * 128 + (k0 - 128));
            else {
                int ge = e0 + row; if (ge >= N_EDGES) ge = N_EDGES - 1;
                v = *(const float4*)(edge_attr + (size_t)ge * 32 + (k0 - 256));
            }
            uint4 u = make_uint4(f2tf(v.x), f2tf(v.y), f2tf(v.z), f2tf(v.w));
            *(uint4*)(sAu + row * 36 + kk4 * 4) = u;
        }
        #pragma unroll
        for (int t = 0; t < 4; t++) {
            int idx4 = tid + t * 256;
            int k = idx4 >> 5, c4 = idx4 & 31;
            float4 v = *(const float4*)(Wc1 + (size_t)(kc * 32 + k) * 128 + c4 * 4);
            uint4 u = make_uint4(f2tf(v.x), f2tf(v.y), f2tf(v.z), f2tf(v.w));
            *(uint4*)(sBu + k * 132 + c4 * 4) = u;
        }
        __syncthreads();
        #pragma unroll
        for (int ks = 0; ks < 4; ks++) {
            int k0 = ks * 8;
            uint32_t a0 = sAu[r0 * 36 + k0 + tig];
            uint32_t a1 = sAu[(r0 + 8) * 36 + k0 + tig];
            uint32_t a2 = sAu[r0 * 36 + k0 + tig + 4];
            uint32_t a3 = sAu[(r0 + 8) * 36 + k0 + tig + 4];
            #pragma unroll
            for (int t = 0; t < 16; t++) {
                uint32_t b0 = sBu[(k0 + tig) * 132 + t * 8 + g];
                uint32_t b1 = sBu[(k0 + tig + 4) * 132 + t * 8 + g];
                mma_tf32(acc[t], a0, a1, a2, a3, b0, b1);
            }
        }
        __syncthreads();
    }
    #pragma unroll
    for (int t = 0; t < 16; t++) {
        int c = t * 8 + tig * 2;
        float bb0 = bc1[c], bb1 = bc1[c + 1];
        sh1u[r0 * 132 + c]           = f2tf(fmaxf(acc[t][0] + bb0, 0.f));
        sh1u[r0 * 132 + c + 1]       = f2tf(fmaxf(acc[t][1] + bb1, 0.f));
        sh1u[(r0 + 8) * 132 + c]     = f2tf(fmaxf(acc[t][2] + bb0, 0.f));
        sh1u[(r0 + 8) * 132 + c + 1] = f2tf(fmaxf(acc[t][3] + bb1, 0.f));
    }
    __syncthreads();

    float acc2[8][4];
    #pragma unroll
    for (int t = 0; t < 8; t++)
        #pragma unroll
        for (int q = 0; q < 4; q++) acc2[t][q] = 0.f;

    for (int kc = 0; kc < 4; kc++) {
        #pragma unroll
        for (int t = 0; t < 2; t++) {
            int idx4 = tid + t * 256;
            int k = idx4 >> 4, c4 = idx4 & 15;
            float4 v = *(const float4*)(Wc2 + (size_t)(kc * 32 + k) * 64 + c4 * 4);
            uint4 u = make_uint4(f2tf(v.x), f2tf(v.y), f2tf(v.z), f2tf(v.w));
            *(uint4*)(sBu + k * 132 + c4 * 4) = u;
        }
        __syncthreads();
        #pragma unroll
        for (int ks = 0; ks < 4; ks++) {
            int kk = kc * 32 + ks * 8;
            uint32_t a0 = sh1u[r0 * 132 + kk + tig];
            uint32_t a1 = sh1u[(r0 + 8) * 132 + kk + tig];
            uint32_t a2 = sh1u[r0 * 132 + kk + tig + 4];
            uint32_t a3 = sh1u[(r0 + 8) * 132 + kk + tig + 4];
            #pragma unroll
            for (int t = 0; t < 8; t++) {
                uint32_t b0 = sBu[(ks * 8 + tig) * 132 + t * 8 + g];
                uint32_t b1 = sBu[(ks * 8 + tig + 4) * 132 + t * 8 + g];
                mma_tf32(acc2[t], a0, a1, a2, a3, b0, b1);
            }
        }
        __syncthreads();
    }
    #pragma unroll
    for (int t = 0; t < 8; t++) {
        int c = t * 8 + tig * 2;
        float bb0 = bc2[c], bb1 = bc2[c + 1];
        sh2[r0 * 68 + c]           = fmaxf(acc2[t][0] + bb0, 0.f);
        sh2[r0 * 68 + c + 1]       = fmaxf(acc2[t][1] + bb1, 0.f);
        sh2[(r0 + 8) * 68 + c]     = fmaxf(acc2[t][2] + bb0, 0.f);
        sh2[(r0 + 8) * 68 + c + 1] = fmaxf(acc2[t][3] + bb1, 0.f);
    }
    __syncthreads();

    {
        int e = tid >> 1;
        int o = tid & 1;
        float s = bc3[o];
        const float* hr = sh2 + e * 68;
        #pragma unroll 8
        for (int k = 0; k < 64; k++) s += hr[k] * Wc3[k * 2 + o];
        int ge = e0 + e;
        if (ge < N_EDGES) out[(size_t)ge * 2 + o] = s;
    }
}

/* ------------------------------------------------------------------ */
/* launch: dual-stream overlap (R11 structure, no-lmax kernels)        */
/* ------------------------------------------------------------------ */
extern "C" void kernel_launch(void* const* d_in, const int* in_sizes, int n_in,
                              void* d_out, int out_size) {
    (void)in_sizes; (void)n_in; (void)out_size;
    const float* x     = (const float*)d_in[0];
    const int*   ei    = (const int*)d_in[1];
    const float* ea    = (const float*)d_in[2];
    /* d_in[3] global_ids unused */
    const float* Wl1 = (const float*)d_in[4];
    const float* bl1 = (const float*)d_in[5];
    const float* Wr1 = (const float*)d_in[6];
    const float* br1 = (const float*)d_in[7];
    const float* We1 = (const float*)d_in[8];
    const float* att1 = (const float*)d_in[9];
    const float* bias1 = (const float*)d_in[10];
    const float* Wl2 = (const float*)d_in[11];
    const float* bl2 = (const float*)d_in[12];
    const float* Wr2 = (const float*)d_in[13];
    const float* br2 = (const float*)d_in[14];
    const float* We2 = (const float*)d_in[15];
    const float* att2 = (const float*)d_in[16];
    const float* bias2 = (const float*)d_in[17];
    const float* W_ih = (const float*)d_in[18];
    /* d_in[19] W_hh unused: h_prev == 0 */
    const float* b_ih = (const float*)d_in[20];
    const float* b_hh = (const float*)d_in[21];
    const float* Wc1 = (const float*)d_in[22];
    const float* bc1 = (const float*)d_in[23];
    const float* Wc2 = (const float*)d_in[24];
    const float* bc2 = (const float*)d_in[25];
    const float* Wc3 = (const float*)d_in[26];
    const float* bc3 = (const float*)d_in[27];
    float* out = (float*)d_out;

    float *p_xl, *p_xr, *p_z1, *p_z2, *p_gi, *p_lea1, *p_lea2;
    cudaGetSymbolAddress((void**)&p_xl, g_xl);
    cudaGetSymbolAddress((void**)&p_xr, g_xr);
    cudaGetSymbolAddress((void**)&p_z1, g_z1);
    cudaGetSymbolAddress((void**)&p_z2, g_z2);
    cudaGetSymbolAddress((void**)&p_gi, g_gi);
    cudaGetSymbolAddress((void**)&p_lea1, g_loop_ea1);
    cudaGetSymbolAddress((void**)&p_lea2, g_loop_ea2);

    /* one-time setup (first call is the uncaptured correctness run) */
    static int setup_done = 0;
    static cudaStream_t s2;
    static cudaEvent_t ev0, evL, evCSR, evAgg1, evX2;
    if (!setup_done) {
        cudaFuncSetAttribute(k_cls, cudaFuncAttributeMaxDynamicSharedMemorySize,
                             CLS_SMEM_BYTES);
        cudaStreamCreateWithFlags(&s2, cudaStreamNonBlocking);
        cudaEventCreateWithFlags(&ev0,   cudaEventDisableTiming);
        cudaEventCreateWithFlags(&evL,   cudaEventDisableTiming);
        cudaEventCreateWithFlags(&evCSR, cudaEventDisableTiming);
        cudaEventCreateWithFlags(&evAgg1, cudaEventDisableTiming);
        cudaEventCreateWithFlags(&evX2,  cudaEventDisableTiming);
        setup_done = 1;
    }

    dim3 tb(256);
    int gy = (N_NODES + 127) / 128;
    int logit_blocks_l1 = (N_EDGES / 8 * 2 + 7) / 8;
    int logit_blocks_l2 = (N_EDGES / 8 + 7) / 8;

    /* main: init, then the layer-1 GEMM+logit chain (logit8h2 = 4th launch) */
    k_init<<<(N_NODES + 255) / 256, 256>>>();
    cudaEventRecord(ev0, 0);
    k_gemm<false><<<dim3(2, gy), tb>>>(x, Wl1, bl1, p_xl, N_NODES, 256);
    k_gemm<false><<<dim3(2, gy), tb>>>(x, Wr1, br1, p_xr, N_NODES, 256);
    k_logit8h2<<<logit_blocks_l1, 256>>>(ei, ea, We1, att1);

    /* side stream: easum/loopea + CSR build, forked after k_init */
    cudaStreamWaitEvent(s2, ev0, 0);
    k_easum<<<(N_EDGES + 1023) / 1024, 256, 0, s2>>>(ea);
    k_loopea<<<1, 256, 0, s2>>>(We1, We2);
    cudaEventRecord(evL, s2);
    k_deg<<<(EF + 255) / 256, 256, 0, s2>>>(ei);
    k_blocksum<<<NB_SCAN, 256, 0, s2>>>();
    k_scanb<<<1, 256, 0, s2>>>();
    k_scanfinal<<<NB_SCAN, 256, 0, s2>>>();
    k_scatter<<<(EF + 255) / 256, 256, 0, s2>>>(ei);
    cudaEventRecord(evCSR, s2);

    /* main: self-loop logits need loopea; agg needs CSR */
    cudaStreamWaitEvent(0, evL, 0);
    k_logit_self<2><<<(N_NODES + 7) / 8, 256>>>(att1, p_lea1);
    cudaStreamWaitEvent(0, evCSR, 0);
    k_agg<2><<<(N_NODES + 7) / 8, 256>>>(ei, bias1, p_z1);
    cudaEventRecord(evAgg1, 0);

    /* layer 2: xl2 on main, xr2 concurrent on s2 */
    cudaStreamWaitEvent(s2, evAgg1, 0);
    k_gemm<false><<<dim3(1, gy), tb, 0, s2>>>(p_z1, Wr2, br2, p_xr, N_NODES, 128);
    cudaEventRecord(evX2, s2);
    k_gemm<false><<<dim3(1, gy), tb>>>(p_z1, Wl2, bl2, p_xl, N_NODES, 128);
    cudaStreamWaitEvent(0, evX2, 0);
    k_logit8_l2<<<logit_blocks_l2, 256>>>(ei, ea, We2, att2);
    k_logit_self<1><<<(N_NODES + 7) / 8, 256>>>(att2, p_lea2);
    k_agg<1><<<(N_NODES + 7) / 8, 256>>>(ei, bias2, p_z2);

    /* GRU (h_prev = 0) */
    k_gemm<true><<<dim3(3, gy), tb>>>(p_z2, W_ih, b_ih, p_gi, N_NODES, 384);
    k_gru<<<(N_NODES * 128 + 255) / 256, 256>>>(b_hh);

    /* edge classifier (tf32 tensor cores) */
    k_cls<<<(N_EDGES + 127) / 128, 256, CLS_SMEM_BYTES>>>(
        ei, ea, Wc1, bc1, Wc2, bc2, Wc3, bc3, out);
}

// round 14
// speedup vs baseline: 1.0851x; 1.0630x over previous
#include <cuda_runtime.h>
#include <math.h>
#include <stdint.h>

#define N_NODES 50000
#define N_EDGES 500000
#define EF (N_EDGES + N_NODES)  /* 550000 */
#define NB_SCAN 196             /* ceil(N_NODES/256) */

/* ------------------------------------------------------------------ */
/* scratch (static device memory; no runtime allocation allowed)       */
/* ------------------------------------------------------------------ */
__device__ float g_xl[N_NODES * 256];
__device__ float g_xr[N_NODES * 256];
__device__ float g_z1[N_NODES * 128];
__device__ float g_z2[N_NODES * 128];
__device__ float g_gi[N_NODES * 384];
__device__ float g_h [N_NODES * 128];
__device__ float g_logit[EF * 2];
__device__ int   g_deg[N_NODES];
__device__ int   g_cursor[N_NODES];
__device__ int   g_off[N_NODES + 1];
__device__ int   g_eidx[EF];
__device__ float g_easum[32];
__device__ float g_loop_ea1[256];
__device__ float g_loop_ea2[128];
__device__ int   g_bsum[256];
__device__ int   g_bexcl[256];

/* ------------------------------------------------------------------ */
__device__ __forceinline__ uint32_t f2tf(float f) {
    uint32_t u;
    asm("cvt.rna.tf32.f32 %0, %1;" : "=r"(u) : "f"(f));
    return u;
}

__device__ __forceinline__ void mma_tf32(float* c,
        uint32_t a0, uint32_t a1, uint32_t a2, uint32_t a3,
        uint32_t b0, uint32_t b1) {
    asm volatile(
        "mma.sync.aligned.m16n8k8.row.col.f32.tf32.tf32.f32 "
        "{%0,%1,%2,%3}, {%4,%5,%6,%7}, {%8,%9}, {%0,%1,%2,%3};"
        : "+f"(c[0]), "+f"(c[1]), "+f"(c[2]), "+f"(c[3])
        : "r"(a0), "r"(a1), "r"(a2), "r"(a3), "r"(b0), "r"(b1));
}

/* ------------------------------------------------------------------ */
/* init / edge_attr mean / loop edge features                          */
/* ------------------------------------------------------------------ */
__global__ void k_init() {
    int i = blockIdx.x * blockDim.x + threadIdx.x;
    if (i < N_NODES) { g_deg[i] = 0; g_cursor[i] = 0; }
    if (i < 32) g_easum[i] = 0.f;
}

__global__ void k_easum(const float* __restrict__ ea) {
    __shared__ float s[8][32];
    int d = threadIdx.x & 31;
    int r = threadIdx.x >> 5;
    int base = blockIdx.x * 1024;
    int end  = base + 1024; if (end > N_EDGES) end = N_EDGES;
    float acc = 0.f;
    for (int e = base + r; e < end; e += 8)
        acc += ea[(size_t)e * 32 + d];
    s[r][d] = acc;
    __syncthreads();
    if (r == 0) {
        float t = 0.f;
        #pragma unroll
        for (int i = 0; i < 8; i++) t += s[i][d];
        atomicAdd(&g_easum[d], t);
    }
}

__global__ void k_loopea(const float* __restrict__ We1, const float* __restrict__ We2) {
    int j = threadIdx.x;
    float inv = 1.f / (float)N_EDGES;
    if (j < 256) {
        float s = 0.f;
        for (int d = 0; d < 32; d++) s += g_easum[d] * inv * We1[d * 256 + j];
        g_loop_ea1[j] = s;
    }
    if (j < 128) {
        float s = 0.f;
        for (int d = 0; d < 32; d++) s += g_easum[d] * inv * We2[d * 128 + j];
        g_loop_ea2[j] = s;
    }
}

/* ------------------------------------------------------------------ */
/* CSR build                                                           */
/* ------------------------------------------------------------------ */
__global__ void k_deg(const int* __restrict__ ei) {
    int e = blockIdx.x * blockDim.x + threadIdx.x;
    if (e >= EF) return;
    int dst = (e < N_EDGES) ? ei[N_EDGES + e] : (e - N_EDGES);
    atomicAdd(&g_deg[dst], 1);
}

__global__ void k_blocksum() {
    __shared__ int s[256];
    int i = blockIdx.x * 256 + threadIdx.x;
    s[threadIdx.x] = (i < N_NODES) ? g_deg[i] : 0;
    __syncthreads();
    for (int o = 128; o > 0; o >>= 1) {
        if (threadIdx.x < o) s[threadIdx.x] += s[threadIdx.x + o];
        __syncthreads();
    }
    if (threadIdx.x == 0) g_bsum[blockIdx.x] = s[0];
}

__global__ void k_scanb() {
    __shared__ int s[256];
    int t = threadIdx.x;
    int v = (t < NB_SCAN) ? g_bsum[t] : 0;
    s[t] = v;
    __syncthreads();
    for (int d = 1; d < 256; d <<= 1) {
        int x = (t >= d) ? s[t - d] : 0;
        __syncthreads();
        s[t] += x;
        __syncthreads();
    }
    g_bexcl[t] = s[t] - v;
}

__global__ void k_scanfinal() {
    __shared__ int s[256];
    int t = threadIdx.x;
    int i = blockIdx.x * 256 + t;
    int v = (i < N_NODES) ? g_deg[i] : 0;
    s[t] = v;
    __syncthreads();
    for (int d = 1; d < 256; d <<= 1) {
        int x = (t >= d) ? s[t - d] : 0;
        __syncthreads();
        s[t] += x;
        __syncthreads();
    }
    if (i < N_NODES) g_off[i] = g_bexcl[blockIdx.x] + s[t] - v;
    if (i == 0) g_off[N_NODES] = EF;
}

__global__ void k_scatter(const int* __restrict__ ei) {
    int e = blockIdx.x * blockDim.x + threadIdx.x;
    if (e >= EF) return;
    int dst = (e < N_EDGES) ? ei[N_EDGES + e] : (e - N_EDGES);
    int pos = atomicAdd(&g_cursor[dst], 1);
    g_eidx[g_off[dst] + pos] = e;
}

/* ------------------------------------------------------------------ */
/* tiled SGEMM  C[M,Nc] = A[M,128] @ B + bias   (fp32)                 */
/* ------------------------------------------------------------------ */
template <bool TRANSB>
__global__ void __launch_bounds__(256) k_gemm(
        const float* __restrict__ A, const float* __restrict__ B,
        const float* __restrict__ bias, float* __restrict__ C,
        int M, int Nc) {
    __shared__ float As[128][36];
    __shared__ float Bs[32][132];
    int tid = threadIdx.x;
    int tx = tid & 15, ty = tid >> 4;
    int row0 = blockIdx.y * 128;
    int col0 = blockIdx.x * 128;
    int j0 = tx * 8;
    float acc[8][8];
    #pragma unroll
    for (int i = 0; i < 8; i++)
        #pragma unroll
        for (int j = 0; j < 8; j++) acc[i][j] = 0.f;

    for (int kc = 0; kc < 4; kc++) {
        #pragma unroll
        for (int t = 0; t < 4; t++) {
            int idx4 = tid + t * 256;
            int r = idx4 >> 3, kk4 = idx4 & 7;
            float4 v = make_float4(0.f, 0.f, 0.f, 0.f);
            if (row0 + r < M)
                v = *(const float4*)(A + (size_t)(row0 + r) * 128 + kc * 32 + kk4 * 4);
            *(float4*)&As[r][kk4 * 4] = v;
        }
        if (!TRANSB) {
            #pragma unroll
            for (int t = 0; t < 4; t++) {
                int idx4 = tid + t * 256;
                int k = idx4 >> 5, c4 = idx4 & 31;
                float4 v = *(const float4*)(B + (size_t)(kc * 32 + k) * Nc + col0 + c4 * 4);
                *(float4*)&Bs[k][c4 * 4] = v;
            }
        } else {
            #pragma unroll
            for (int t = 0; t < 4; t++) {
                int idx4 = tid + t * 256;
                int j = idx4 >> 3, k4 = idx4 & 7;
                float4 v = *(const float4*)(B + (size_t)(col0 + j) * 128 + kc * 32 + k4 * 4);
                Bs[k4 * 4 + 0][j] = v.x;
                Bs[k4 * 4 + 1][j] = v.y;
                Bs[k4 * 4 + 2][j] = v.z;
                Bs[k4 * 4 + 3][j] = v.w;
            }
        }
        __syncthreads();
        #pragma unroll 8
        for (int kk = 0; kk < 32; kk++) {
            float4 b0 = *(const float4*)&Bs[kk][j0];
            float4 b1 = *(const float4*)&Bs[kk][j0 + 4];
            #pragma unroll
            for (int i = 0; i < 8; i++) {
                float a = As[ty * 8 + i][kk];
                acc[i][0] += a * b0.x; acc[i][1] += a * b0.y;
                acc[i][2] += a * b0.z; acc[i][3] += a * b0.w;
                acc[i][4] += a * b1.x; acc[i][5] += a * b1.y;
                acc[i][6] += a * b1.z; acc[i][7] += a * b1.w;
            }
        }
        __syncthreads();
    }
    float4 bv0 = *(const float4*)(bias + col0 + j0);
    float4 bv1 = *(const float4*)(bias + col0 + j0 + 4);
    #pragma unroll
    for (int i = 0; i < 8; i++) {
        int r = row0 + ty * 8 + i;
        if (r < M) {
            float4 o0, o1;
            o0.x = acc[i][0] + bv0.x; o0.y = acc[i][1] + bv0.y;
            o0.z = acc[i][2] + bv0.z; o0.w = acc[i][3] + bv0.w;
            o1.x = acc[i][4] + bv1.x; o1.y = acc[i][5] + bv1.y;
            o1.z = acc[i][6] + bv1.z; o1.w = acc[i][7] + bv1.w;
            *(float4*)(C + (size_t)r * Nc + col0 + j0) = o0;
            *(float4*)(C + (size_t)r * Nc + col0 + j0 + 4) = o1;
        }
    }
}

/* ------------------------------------------------------------------ */
/* layer-1 logits, fused tf32-mma: block = 64 edges                    */
/* phase A: stage We1 + ea tile (tf32); phase B: ev = ea@We1 via mma   */
/* into smem; phase C: logit = dot(leaky(xl+xr+ev), att), no lmax      */
/* smem: sW [32][260] 33280 | sA [64][36] 9216 | sEV [64][260] 66560   */
/* ------------------------------------------------------------------ */
#define L1_SMEM_BYTES 109056

__global__ void __launch_bounds__(256) k_logit_mma_l1(
        const int* __restrict__ ei, const float* __restrict__ edge_attr,
        const float* __restrict__ We, const float* __restrict__ att) {
    extern __shared__ char smem[];
    uint32_t* sW  = (uint32_t*)(smem);            /* [32][260] tf32 */
    uint32_t* sA  = (uint32_t*)(smem + 33280);    /* [64][36]  tf32 */
    float*    sEV = (float*)(smem + 42496);       /* [64][260] fp32 */

    int tid = threadIdx.x;
    int e0 = blockIdx.x * 64;

    /* phase A: We1 (32x256) + ea tile (64x32), converted to tf32 */
    #pragma unroll
    for (int t = 0; t < 8; t++) {
        int idx4 = tid + t * 256;
        int k = idx4 >> 6, c4 = idx4 & 63;
        float4 v = *(const float4*)(We + k * 256 + c4 * 4);
        uint4 u = make_uint4(f2tf(v.x), f2tf(v.y), f2tf(v.z), f2tf(v.w));
        *(uint4*)(sW + k * 260 + c4 * 4) = u;
    }
    #pragma unroll
    for (int t = 0; t < 2; t++) {
        int idx4 = tid + t * 256;
        int row = idx4 >> 3, kk4 = idx4 & 7;
        int ge = e0 + row; if (ge >= N_EDGES) ge = N_EDGES - 1;
        float4 v = *(const float4*)(edge_attr + (size_t)ge * 32 + kk4 * 4);
        uint4 u = make_uint4(f2tf(v.x), f2tf(v.y), f2tf(v.z), f2tf(v.w));
        *(uint4*)(sA + row * 36 + kk4 * 4) = u;
    }
    __syncthreads();

    int lane = tid & 31, w = tid >> 5;
    int g = lane >> 2, tig = lane & 3;
    int mt = w & 3, nh = w >> 2;
    int r0 = mt * 16 + g;
    int nb = nh * 128;

    /* phase B: M64 x N256 x K32 mma */
    float acc[16][4];
    #pragma unroll
    for (int t = 0; t < 16; t++)
        #pragma unroll
        for (int q = 0; q < 4; q++) acc[t][q] = 0.f;

    #pragma unroll
    for (int ks = 0; ks < 4; ks++) {
        int k0 = ks * 8;
        uint32_t a0 = sA[r0 * 36 + k0 + tig];
        uint32_t a1 = sA[(r0 + 8) * 36 + k0 + tig];
        uint32_t a2 = sA[r0 * 36 + k0 + tig + 4];
        uint32_t a3 = sA[(r0 + 8) * 36 + k0 + tig + 4];
        #pragma unroll
        for (int t = 0; t < 16; t++) {
            uint32_t b0 = sW[(k0 + tig) * 260 + nb + t * 8 + g];
            uint32_t b1 = sW[(k0 + tig + 4) * 260 + nb + t * 8 + g];
            mma_tf32(acc[t], a0, a1, a2, a3, b0, b1);
        }
    }
    #pragma unroll
    for (int t = 0; t < 16; t++) {
        int c = nb + t * 8 + tig * 2;
        sEV[r0 * 260 + c]           = acc[t][0];
        sEV[r0 * 260 + c + 1]       = acc[t][1];
        sEV[(r0 + 8) * 260 + c]     = acc[t][2];
        sEV[(r0 + 8) * 260 + c + 1] = acc[t][3];
    }
    __syncthreads();

    /* phase C: warp w -> edges e0 + w*8 .. +7, both heads */
    int c0 = lane * 8;
    const float4* ap = (const float4*)(att + c0);
    float4 at0 = ap[0], at1 = ap[1];
    #pragma unroll
    for (int j = 0; j < 8; j++) {
        int le = w * 8 + j;
        int e = e0 + le;
        int ce = (e < N_EDGES) ? e : N_EDGES - 1;
        int src = ei[ce];
        int dst = ei[N_EDGES + ce];
        const float4* xlp = (const float4*)(g_xl + (size_t)src * 256 + c0);
        const float4* xrp = (const float4*)(g_xr + (size_t)dst * 256 + c0);
        const float4* evp = (const float4*)(sEV + le * 260 + c0);
        float4 ev0 = evp[0], ev1 = evp[1];
        float s = 0.f, m;
        {
            float4 a = xlp[0], b = xrp[0];
            m = a.x + b.x + ev0.x; m = (m > 0.f) ? m : 0.2f * m; s += m * at0.x;
            m = a.y + b.y + ev0.y; m = (m > 0.f) ? m : 0.2f * m; s += m * at0.y;
            m = a.z + b.z + ev0.z; m = (m > 0.f) ? m : 0.2f * m; s += m * at0.z;
            m = a.w + b.w + ev0.w; m = (m > 0.f) ? m : 0.2f * m; s += m * at0.w;
        }
        {
            float4 a = xlp[1], b = xrp[1];
            m = a.x + b.x + ev1.x; m = (m > 0.f) ? m : 0.2f * m; s += m * at1.x;
            m = a.y + b.y + ev1.y; m = (m > 0.f) ? m : 0.2f * m; s += m * at1.y;
            m = a.z + b.z + ev1.z; m = (m > 0.f) ? m : 0.2f * m; s += m * at1.z;
            m = a.w + b.w + ev1.w; m = (m > 0.f) ? m : 0.2f * m; s += m * at1.w;
        }
        #pragma unroll
        for (int o = 8; o > 0; o >>= 1) s += __shfl_xor_sync(0xffffffffu, s, o);
        if ((lane & 15) == 0 && e < N_EDGES)
            g_logit[(size_t)e * 2 + (lane >> 4)] = s;
    }
}

/* ------------------------------------------------------------------ */
/* layer-2 logits, fused tf32-mma: block = 64 edges, N=128             */
/* smem: sW [32][132] 16896 | sA [64][36] 9216 | sEV [64][132] 33792   */
/* ------------------------------------------------------------------ */
#define L2_SMEM_BYTES 59904

__global__ void __launch_bounds__(256) k_logit_mma_l2(
        const int* __restrict__ ei, const float* __restrict__ edge_attr,
        const float* __restrict__ We, const float* __restrict__ att) {
    extern __shared__ char smem[];
    uint32_t* sW  = (uint32_t*)(smem);            /* [32][132] tf32 */
    uint32_t* sA  = (uint32_t*)(smem + 16896);    /* [64][36]  tf32 */
    float*    sEV = (float*)(smem + 26112);       /* [64][132] fp32 */

    int tid = threadIdx.x;
    int e0 = blockIdx.x * 64;

    #pragma unroll
    for (int t = 0; t < 4; t++) {
        int idx4 = tid + t * 256;
        int k = idx4 >> 5, c4 = idx4 & 31;
        float4 v = *(const float4*)(We + k * 128 + c4 * 4);
        uint4 u = make_uint4(f2tf(v.x), f2tf(v.y), f2tf(v.z), f2tf(v.w));
        *(uint4*)(sW + k * 132 + c4 * 4) = u;
    }
    #pragma unroll
    for (int t = 0; t < 2; t++) {
        int idx4 = tid + t * 256;
        int row = idx4 >> 3, kk4 = idx4 & 7;
        int ge = e0 + row; if (ge >= N_EDGES) ge = N_EDGES - 1;
        float4 v = *(const float4*)(edge_attr + (size_t)ge * 32 + kk4 * 4);
        uint4 u = make_uint4(f2tf(v.x), f2tf(v.y), f2tf(v.z), f2tf(v.w));
        *(uint4*)(sA + row * 36 + kk4 * 4) = u;
    }
    __syncthreads();

    int lane = tid & 31, w = tid >> 5;
    int g = lane >> 2, tig = lane & 3;
    int mt = w & 3, nh = w >> 2;
    int r0 = mt * 16 + g;
    int nb = nh * 64;

    float acc[8][4];
    #pragma unroll
    for (int t = 0; t < 8; t++)
        #pragma unroll
        for (int q = 0; q < 4; q++) acc[t][q] = 0.f;

    #pragma unroll
    for (int ks = 0; ks < 4; ks++) {
        int k0 = ks * 8;
        uint32_t a0 = sA[r0 * 36 + k0 + tig];
        uint32_t a1 = sA[(r0 + 8) * 36 + k0 + tig];
        uint32_t a2 = sA[r0 * 36 + k0 + tig + 4];
        uint32_t a3 = sA[(r0 + 8) * 36 + k0 + tig + 4];
        #pragma unroll
        for (int t = 0; t < 8; t++) {
            uint32_t b0 = sW[(k0 + tig) * 132 + nb + t * 8 + g];
            uint32_t b1 = sW[(k0 + tig + 4) * 132 + nb + t * 8 + g];
            mma_tf32(acc[t], a0, a1, a2, a3, b0, b1);
        }
    }
    #pragma unroll
    for (int t = 0; t < 8; t++) {
        int c = nb + t * 8 + tig * 2;
        sEV[r0 * 132 + c]           = acc[t][0];
        sEV[r0 * 132 + c + 1]       = acc[t][1];
        sEV[(r0 + 8) * 132 + c]     = acc[t][2];
        sEV[(r0 + 8) * 132 + c + 1] = acc[t][3];
    }
    __syncthreads();

    int c0 = lane * 4;
    float4 at = *(const float4*)(att + c0);
    #pragma unroll
    for (int j = 0; j < 8; j++) {
        int le = w * 8 + j;
        int e = e0 + le;
        int ce = (e < N_EDGES) ? e : N_EDGES - 1;
        int src = ei[ce];
        int dst = ei[N_EDGES + ce];
        float4 a = *(const float4*)(g_xl + (size_t)src * 128 + c0);
        float4 b = *(const float4*)(g_xr + (size_t)dst * 128 + c0);
        float4 ev = *(const float4*)(sEV + le * 132 + c0);
        float s = 0.f, m;
        m = a.x + b.x + ev.x; m = (m > 0.f) ? m : 0.2f * m; s += m * at.x;
        m = a.y + b.y + ev.y; m = (m > 0.f) ? m : 0.2f * m; s += m * at.y;
        m = a.z + b.z + ev.z; m = (m > 0.f) ? m : 0.2f * m; s += m * at.z;
        m = a.w + b.w + ev.w; m = (m > 0.f) ? m : 0.2f * m; s += m * at.w;
        #pragma unroll
        for (int o = 16; o > 0; o >>= 1) s += __shfl_xor_sync(0xffffffffu, s, o);
        if (lane == 0 && e < N_EDGES)
            g_logit[e] = s;
    }
}

/* self-loop logits: warp per node, no lmax */
template <int H>
__global__ void k_logit_self(const float* __restrict__ att,
                             const float* __restrict__ loop_ea) {
    const int HC = H * 128;
    const int CPL = HC / 32;
    int n = (blockIdx.x * blockDim.x + threadIdx.x) >> 5;
    if (n >= N_NODES) return;
    int lane = threadIdx.x & 31;
    int c0 = lane * CPL;
    const float4* xlp = (const float4*)(g_xl + (size_t)n * HC + c0);
    const float4* xrp = (const float4*)(g_xr + (size_t)n * HC + c0);
    const float4* lp  = (const float4*)(loop_ea + c0);
    const float4* ap  = (const float4*)(att + c0);
    float s = 0.f;
    #pragma unroll
    for (int q4 = 0; q4 < CPL / 4; q4++) {
        float4 a = xlp[q4], b = xrp[q4], e = lp[q4], at = ap[q4];
        float m;
        m = a.x + b.x + e.x; m = (m > 0.f) ? m : 0.2f * m; s += m * at.x;
        m = a.y + b.y + e.y; m = (m > 0.f) ? m : 0.2f * m; s += m * at.y;
        m = a.z + b.z + e.z; m = (m > 0.f) ? m : 0.2f * m; s += m * at.z;
        m = a.w + b.w + e.w; m = (m > 0.f) ? m : 0.2f * m; s += m * at.w;
    }
    if (H == 2) {
        #pragma unroll
        for (int o = 8; o > 0; o >>= 1) s += __shfl_xor_sync(0xffffffffu, s, o);
        if ((lane & 15) == 0) {
            int h = lane >> 4;
            g_logit[(size_t)(N_EDGES + n) * 2 + h] = s;
        }
    } else {
        #pragma unroll
        for (int o = 16; o > 0; o >>= 1) s += __shfl_xor_sync(0xffffffffu, s, o);
        if (lane == 0)
            g_logit[N_EDGES + n] = s;
    }
}

/* ------------------------------------------------------------------ */
/* aggregation, fused softmax (no lmax): warp per dst node, CSR        */
/* ------------------------------------------------------------------ */
template <int H>
__global__ void k_agg(const int* __restrict__ ei, const float* __restrict__ bias,
                      float* __restrict__ z) {
    const int HC = H * 128;
    const int CPL = HC / 32;
    int n = (blockIdx.x * blockDim.x + threadIdx.x) >> 5;
    if (n >= N_NODES) return;
    int lane = threadIdx.x & 31;
    int c0 = lane * CPL;
    int h = (H == 2) ? (lane >> 4) : 0;
    float sum_p = 0.f;
    float acc[8];
    #pragma unroll
    for (int q = 0; q < CPL; q++) acc[q] = 0.f;
    int b0 = g_off[n], b1 = g_off[n + 1];
    for (int idx = b0; idx < b1; idx++) {
        int e = g_eidx[idx];
        int src = (e < N_EDGES) ? ei[e] : n;
        float p = __expf(g_logit[(size_t)e * H + h]);
        sum_p += p;
        const float4* xp = (const float4*)(g_xl + (size_t)src * HC + c0);
        #pragma unroll
        for (int q4 = 0; q4 < CPL / 4; q4++) {
            float4 v = xp[q4];
            acc[q4 * 4 + 0] += p * v.x;
            acc[q4 * 4 + 1] += p * v.y;
            acc[q4 * 4 + 2] += p * v.z;
            acc[q4 * 4 + 3] += p * v.w;
        }
    }
    float inv = 1.f / sum_p;
    #pragma unroll
    for (int q = 0; q < CPL; q++) acc[q] *= inv;
    if (H == 2) {
        #pragma unroll
        for (int q = 0; q < 8; q++)
            acc[q] = 0.5f * (acc[q] + __shfl_xor_sync(0xffffffffu, acc[q], 16));
        if (lane < 16) {
            int c = lane * 8;
            float4 o0, o1;
            float v;
            v = acc[0] + bias[c + 0]; o0.x = (v > 0.f) ? v : expm1f(v);
            v = acc[1] + bias[c + 1]; o0.y = (v > 0.f) ? v : expm1f(v);
            v = acc[2] + bias[c + 2]; o0.z = (v > 0.f) ? v : expm1f(v);
            v = acc[3] + bias[c + 3]; o0.w = (v > 0.f) ? v : expm1f(v);
            v = acc[4] + bias[c + 4]; o1.x = (v > 0.f) ? v : expm1f(v);
            v = acc[5] + bias[c + 5]; o1.y = (v > 0.f) ? v : expm1f(v);
            v = acc[6] + bias[c + 6]; o1.z = (v > 0.f) ? v : expm1f(v);
            v = acc[7] + bias[c + 7]; o1.w = (v > 0.f) ? v : expm1f(v);
            *(float4*)(z + (size_t)n * 128 + c) = o0;
            *(float4*)(z + (size_t)n * 128 + c + 4) = o1;
        }
    } else {
        int c = lane * 4;
        float4 o;
        float v;
        v = acc[0] + bias[c + 0]; o.x = (v > 0.f) ? v : expm1f(v);
        v = acc[1] + bias[c + 1]; o.y = (v > 0.f) ? v : expm1f(v);
        v = acc[2] + bias[c + 2]; o.z = (v > 0.f) ? v : expm1f(v);
        v = acc[3] + bias[c + 3]; o.w = (v > 0.f) ? v : expm1f(v);
        *(float4*)(z + (size_t)n * 128 + c) = o;
    }
}

/* ------------------------------------------------------------------ */
/* GRU (h_prev = 0): h = (1-u)*g                                       */
/* ------------------------------------------------------------------ */
__global__ void k_gru(const float* __restrict__ b_hh) {
    int i = blockIdx.x * blockDim.x + threadIdx.x;
    if (i >= N_NODES * 128) return;
    int n = i >> 7;
    int c = i & 127;
    const float* gi = g_gi + (size_t)n * 384;
    float r = 1.f / (1.f + __expf(-(gi[c] + b_hh[c])));
    float u = 1.f / (1.f + __expf(-(gi[128 + c] + b_hh[128 + c])));
    float g = tanhf(gi[256 + c] + r * b_hh[256 + c]);
    g_h[i] = (1.f - u) * g;
}

/* ------------------------------------------------------------------ */
/* fused edge classifier, tf32 tensor cores                            */
/* ------------------------------------------------------------------ */
#define CLS_SMEM_BYTES 103936

__global__ void __launch_bounds__(256) k_cls(
        const int* __restrict__ ei, const float* __restrict__ edge_attr,
        const float* __restrict__ Wc1, const float* __restrict__ bc1,
        const float* __restrict__ Wc2, const float* __restrict__ bc2,
        const float* __restrict__ Wc3, const float* __restrict__ bc3,
        float* __restrict__ out) {
    extern __shared__ char smem[];
    int*      s_src = (int*)smem;
    int*      s_dst = (int*)(smem + 512);
    uint32_t* sAu   = (uint32_t*)(smem + 1024);    /* [128][36]  tf32 */
    uint32_t* sBu   = (uint32_t*)(smem + 19456);   /* [32][132]  tf32 */
    uint32_t* sh1u  = (uint32_t*)(smem + 36352);   /* [128][132] tf32 */
    float*    sh2   = (float*)(smem + 1024);       /* [128][68] fp32 overlay */

    int tid = threadIdx.x;
    int e0 = blockIdx.x * 128;
    {
        int ge = e0 + (tid & 127);
        if (ge >= N_EDGES) ge = N_EDGES - 1;
        if (tid < 128) s_src[tid] = ei[ge];
        else           s_dst[tid - 128] = ei[N_EDGES + ge];
    }
    __syncthreads();

    int lane = tid & 31, w = tid >> 5;
    int g = lane >> 2, tig = lane & 3;
    int r0 = w * 16 + g;

    float acc[16][4];
    #pragma unroll
    for (int t = 0; t < 16; t++)
        #pragma unroll
        for (int q = 0; q < 4; q++) acc[t][q] = 0.f;

    for (int kc = 0; kc < 9; kc++) {
        #pragma unroll
        for (int t = 0; t < 4; t++) {
            int idx4 = tid + t * 256;
            int row = idx4 >> 3, kk4 = idx4 & 7;
            int k0 = kc * 32 + kk4 * 4;
            float4 v;
            if (kc < 4)
                v = *(const float4*)(g_h + (size_t)s_src[row] * 128 + k0);
            else if (kc < 8)
                v = *(const float4*)(g_h + (size_t)s_dst[row] * 128 + (k0 - 128));
            else {
                int ge = e0 + row; if (ge >= N_EDGES) ge = N_EDGES - 1;
                v = *(const float4*)(edge_attr + (size_t)ge * 32 + (k0 - 256));
            }
            uint4 u = make_uint4(f2tf(v.x), f2tf(v.y), f2tf(v.z), f2tf(v.w));
            *(uint4*)(sAu + row * 36 + kk4 * 4) = u;
        }
        #pragma unroll
        for (int t = 0; t < 4; t++) {
            int idx4 = tid + t * 256;
            int k = idx4 >> 5, c4 = idx4 & 31;
            float4 v = *(const float4*)(Wc1 + (size_t)(kc * 32 + k) * 128 + c4 * 4);
            uint4 u = make_uint4(f2tf(v.x), f2tf(v.y), f2tf(v.z), f2tf(v.w));
            *(uint4*)(sBu + k * 132 + c4 * 4) = u;
        }
        __syncthreads();
        #pragma unroll
        for (int ks = 0; ks < 4; ks++) {
            int k0 = ks * 8;
            uint32_t a0 = sAu[r0 * 36 + k0 + tig];
            uint32_t a1 = sAu[(r0 + 8) * 36 + k0 + tig];
            uint32_t a2 = sAu[r0 * 36 + k0 + tig + 4];
            uint32_t a3 = sAu[(r0 + 8) * 36 + k0 + tig + 4];
            #pragma unroll
            for (int t = 0; t < 16; t++) {
                uint32_t b0 = sBu[(k0 + tig) * 132 + t * 8 + g];
                uint32_t b1 = sBu[(k0 + tig + 4) * 132 + t * 8 + g];
                mma_tf32(acc[t], a0, a1, a2, a3, b0, b1);
            }
        }
        __syncthreads();
    }
    #pragma unroll
    for (int t = 0; t < 16; t++) {
        int c = t * 8 + tig * 2;
        float bb0 = bc1[c], bb1 = bc1[c + 1];
        sh1u[r0 * 132 + c]           = f2tf(fmaxf(acc[t][0] + bb0, 0.f));
        sh1u[r0 * 132 + c + 1]       = f2tf(fmaxf(acc[t][1] + bb1, 0.f));
        sh1u[(r0 + 8) * 132 + c]     = f2tf(fmaxf(acc[t][2] + bb0, 0.f));
        sh1u[(r0 + 8) * 132 + c + 1] = f2tf(fmaxf(acc[t][3] + bb1, 0.f));
    }
    __syncthreads();

    float acc2[8][4];
    #pragma unroll
    for (int t = 0; t < 8; t++)
        #pragma unroll
        for (int q = 0; q < 4; q++) acc2[t][q] = 0.f;

    for (int kc = 0; kc < 4; kc++) {
        #pragma unroll
        for (int t = 0; t < 2; t++) {
            int idx4 = tid + t * 256;
            int k = idx4 >> 4, c4 = idx4 & 15;
            float4 v = *(const float4*)(Wc2 + (size_t)(kc * 32 + k) * 64 + c4 * 4);
            uint4 u = make_uint4(f2tf(v.x), f2tf(v.y), f2tf(v.z), f2tf(v.w));
            *(uint4*)(sBu + k * 132 + c4 * 4) = u;
        }
        __syncthreads();
        #pragma unroll
        for (int ks = 0; ks < 4; ks++) {
            int kk = kc * 32 + ks * 8;
            uint32_t a0 = sh1u[r0 * 132 + kk + tig];
            uint32_t a1 = sh1u[(r0 + 8) * 132 + kk + tig];
            uint32_t a2 = sh1u[r0 * 132 + kk + tig + 4];
            uint32_t a3 = sh1u[(r0 + 8) * 132 + kk + tig + 4];
            #pragma unroll
            for (int t = 0; t < 8; t++) {
                uint32_t b0 = sBu[(ks * 8 + tig) * 132 + t * 8 + g];
                uint32_t b1 = sBu[(ks * 8 + tig + 4) * 132 + t * 8 + g];
                mma_tf32(acc2[t], a0, a1, a2, a3, b0, b1);
            }
        }
        __syncthreads();
    }
    #pragma unroll
    for (int t = 0; t < 8; t++) {
        int c = t * 8 + tig * 2;
        float bb0 = bc2[c], bb1 = bc2[c + 1];
        sh2[r0 * 68 + c]           = fmaxf(acc2[t][0] + bb0, 0.f);
        sh2[r0 * 68 + c + 1]       = fmaxf(acc2[t][1] + bb1, 0.f);
        sh2[(r0 + 8) * 68 + c]     = fmaxf(acc2[t][2] + bb0, 0.f);
        sh2[(r0 + 8) * 68 + c + 1] = fmaxf(acc2[t][3] + bb1, 0.f);
    }
    __syncthreads();

    {
        int e = tid >> 1;
        int o = tid & 1;
        float s = bc3[o];
        const float* hr = sh2 + e * 68;
        #pragma unroll 8
        for (int k = 0; k < 64; k++) s += hr[k] * Wc3[k * 2 + o];
        int ge = e0 + e;
        if (ge < N_EDGES) out[(size_t)ge * 2 + o] = s;
    }
}

/* ------------------------------------------------------------------ */
/* launch: dual-stream overlap, mma logits                             */
/* ------------------------------------------------------------------ */
extern "C" void kernel_launch(void* const* d_in, const int* in_sizes, int n_in,
                              void* d_out, int out_size) {
    (void)in_sizes; (void)n_in; (void)out_size;
    const float* x     = (const float*)d_in[0];
    const int*   ei    = (const int*)d_in[1];
    const float* ea    = (const float*)d_in[2];
    /* d_in[3] global_ids unused */
    const float* Wl1 = (const float*)d_in[4];
    const float* bl1 = (const float*)d_in[5];
    const float* Wr1 = (const float*)d_in[6];
    const float* br1 = (const float*)d_in[7];
    const float* We1 = (const float*)d_in[8];
    const float* att1 = (const float*)d_in[9];
    const float* bias1 = (const float*)d_in[10];
    const float* Wl2 = (const float*)d_in[11];
    const float* bl2 = (const float*)d_in[12];
    const float* Wr2 = (const float*)d_in[13];
    const float* br2 = (const float*)d_in[14];
    const float* We2 = (const float*)d_in[15];
    const float* att2 = (const float*)d_in[16];
    const float* bias2 = (const float*)d_in[17];
    const float* W_ih = (const float*)d_in[18];
    /* d_in[19] W_hh unused: h_prev == 0 */
    const float* b_ih = (const float*)d_in[20];
    const float* b_hh = (const float*)d_in[21];
    const float* Wc1 = (const float*)d_in[22];
    const float* bc1 = (const float*)d_in[23];
    const float* Wc2 = (const float*)d_in[24];
    const float* bc2 = (const float*)d_in[25];
    const float* Wc3 = (const float*)d_in[26];
    const float* bc3 = (const float*)d_in[27];
    float* out = (float*)d_out;

    float *p_xl, *p_xr, *p_z1, *p_z2, *p_gi, *p_lea1, *p_lea2;
    cudaGetSymbolAddress((void**)&p_xl, g_xl);
    cudaGetSymbolAddress((void**)&p_xr, g_xr);
    cudaGetSymbolAddress((void**)&p_z1, g_z1);
    cudaGetSymbolAddress((void**)&p_z2, g_z2);
    cudaGetSymbolAddress((void**)&p_gi, g_gi);
    cudaGetSymbolAddress((void**)&p_lea1, g_loop_ea1);
    cudaGetSymbolAddress((void**)&p_lea2, g_loop_ea2);

    /* one-time setup (first call is the uncaptured correctness run) */
    static int setup_done = 0;
    static cudaStream_t s2;
    static cudaEvent_t ev0, evL, evCSR, evAgg1, evX2;
    if (!setup_done) {
        cudaFuncSetAttribute(k_cls, cudaFuncAttributeMaxDynamicSharedMemorySize,
                             CLS_SMEM_BYTES);
        cudaFuncSetAttribute(k_logit_mma_l1, cudaFuncAttributeMaxDynamicSharedMemorySize,
                             L1_SMEM_BYTES);
        cudaFuncSetAttribute(k_logit_mma_l2, cudaFuncAttributeMaxDynamicSharedMemorySize,
                             L2_SMEM_BYTES);
        cudaStreamCreateWithFlags(&s2, cudaStreamNonBlocking);
        cudaEventCreateWithFlags(&ev0,   cudaEventDisableTiming);
        cudaEventCreateWithFlags(&evL,   cudaEventDisableTiming);
        cudaEventCreateWithFlags(&evCSR, cudaEventDisableTiming);
        cudaEventCreateWithFlags(&evAgg1, cudaEventDisableTiming);
        cudaEventCreateWithFlags(&evX2,  cudaEventDisableTiming);
        setup_done = 1;
    }

    dim3 tb(256);
    int gy = (N_NODES + 127) / 128;
    int logit_blocks = (N_EDGES + 63) / 64;

    /* main: init, then the layer-1 GEMM+logit chain (logit_mma_l1 = 4th launch) */
    k_init<<<(N_NODES + 255) / 256, 256>>>();
    cudaEventRecord(ev0, 0);
    k_gemm<false><<<dim3(2, gy), tb>>>(x, Wl1, bl1, p_xl, N_NODES, 256);
    k_gemm<false><<<dim3(2, gy), tb>>>(x, Wr1, br1, p_xr, N_NODES, 256);
    k_logit_mma_l1<<<logit_blocks, 256, L1_SMEM_BYTES>>>(ei, ea, We1, att1);

    /* side stream: easum/loopea + CSR build, forked after k_init */
    cudaStreamWaitEvent(s2, ev0, 0);
    k_easum<<<(N_EDGES + 1023) / 1024, 256, 0, s2>>>(ea);
    k_loopea<<<1, 256, 0, s2>>>(We1, We2);
    cudaEventRecord(evL, s2);
    k_deg<<<(EF + 255) / 256, 256, 0, s2>>>(ei);
    k_blocksum<<<NB_SCAN, 256, 0, s2>>>();
    k_scanb<<<1, 256, 0, s2>>>();
    k_scanfinal<<<NB_SCAN, 256, 0, s2>>>();
    k_scatter<<<(EF + 255) / 256, 256, 0, s2>>>(ei);
    cudaEventRecord(evCSR, s2);

    /* main: self-loop logits need loopea; agg needs CSR */
    cudaStreamWaitEvent(0, evL, 0);
    k_logit_self<2><<<(N_NODES + 7) / 8, 256>>>(att1, p_lea1);
    cudaStreamWaitEvent(0, evCSR, 0);
    k_agg<2><<<(N_NODES + 7) / 8, 256>>>(ei, bias1, p_z1);
    cudaEventRecord(evAgg1, 0);

    /* layer 2: xl2 on main, xr2 concurrent on s2 */
    cudaStreamWaitEvent(s2, evAgg1, 0);
    k_gemm<false><<<dim3(1, gy), tb, 0, s2>>>(p_z1, Wr2, br2, p_xr, N_NODES, 128);
    cudaEventRecord(evX2, s2);
    k_gemm<false><<<dim3(1, gy), tb>>>(p_z1, Wl2, bl2, p_xl, N_NODES, 128);
    cudaStreamWaitEvent(0, evX2, 0);
    k_logit_mma_l2<<<logit_blocks, 256, L2_SMEM_BYTES>>>(ei, ea, We2, att2);
    k_logit_self<1><<<(N_NODES + 7) / 8, 256>>>(att2, p_lea2);
    k_agg<1><<<(N_NODES + 7) / 8, 256>>>(ei, bias2, p_z2);

    /* GRU (h_prev = 0) */
    k_gemm<true><<<dim3(3, gy), tb>>>(p_z2, W_ih, b_ih, p_gi, N_NODES, 384);
    k_gru<<<(N_NODES * 128 + 255) / 256, 256>>>(b_hh);

    /* edge classifier (tf32 tensor cores) */
    k_cls<<<(N_EDGES + 127) / 128, 256, CLS_SMEM_BYTES>>>(
        ei, ea, Wc1, bc1, Wc2, bc2, Wc3, bc3, out);
}

// round 15
// speedup vs baseline: 1.2148x; 1.1195x over previous
#include <cuda_runtime.h>
#include <math.h>
#include <stdint.h>

#define N_NODES 50000
#define N_EDGES 500000
#define EF (N_EDGES + N_NODES)  /* 550000 */
#define NB_SCAN 196             /* ceil(N_NODES/256) */

/* ------------------------------------------------------------------ */
/* scratch (static device memory; no runtime allocation allowed)       */
/* ------------------------------------------------------------------ */
__device__ float g_xl[N_NODES * 256];
__device__ float g_xr[N_NODES * 256];
__device__ float g_z1[N_NODES * 128];
__device__ float g_z2[N_NODES * 128];
__device__ float g_gi[N_NODES * 384];
__device__ float g_h [N_NODES * 128];
__device__ float g_logit[EF * 2];
__device__ int   g_deg[N_NODES];
__device__ int   g_cursor[N_NODES];
__device__ int   g_off[N_NODES + 1];
__device__ int   g_eidx[EF];
__device__ int   g_esrc[EF];
__device__ float g_easum[32];
__device__ float g_loop_ea1[256];
__device__ float g_loop_ea2[128];
__device__ int   g_bsum[256];
__device__ int   g_bexcl[256];

/* ------------------------------------------------------------------ */
__device__ __forceinline__ uint32_t f2tf(float f) {
    uint32_t u;
    asm("cvt.rna.tf32.f32 %0, %1;" : "=r"(u) : "f"(f));
    return u;
}

__device__ __forceinline__ void mma_tf32(float* c,
        uint32_t a0, uint32_t a1, uint32_t a2, uint32_t a3,
        uint32_t b0, uint32_t b1) {
    asm volatile(
        "mma.sync.aligned.m16n8k8.row.col.f32.tf32.tf32.f32 "
        "{%0,%1,%2,%3}, {%4,%5,%6,%7}, {%8,%9}, {%0,%1,%2,%3};"
        : "+f"(c[0]), "+f"(c[1]), "+f"(c[2]), "+f"(c[3])
        : "r"(a0), "r"(a1), "r"(a2), "r"(a3), "r"(b0), "r"(b1));
}

/* ------------------------------------------------------------------ */
/* init / edge_attr mean / loop edge features                          */
/* ------------------------------------------------------------------ */
__global__ void k_init() {
    int i = blockIdx.x * blockDim.x + threadIdx.x;
    if (i < N_NODES) { g_deg[i] = 0; g_cursor[i] = 0; }
    if (i < 32) g_easum[i] = 0.f;
}

__global__ void k_easum(const float* __restrict__ ea) {
    __shared__ float s[8][32];
    int d = threadIdx.x & 31;
    int r = threadIdx.x >> 5;
    int base = blockIdx.x * 1024;
    int end  = base + 1024; if (end > N_EDGES) end = N_EDGES;
    float acc = 0.f;
    for (int e = base + r; e < end; e += 8)
        acc += ea[(size_t)e * 32 + d];
    s[r][d] = acc;
    __syncthreads();
    if (r == 0) {
        float t = 0.f;
        #pragma unroll
        for (int i = 0; i < 8; i++) t += s[i][d];
        atomicAdd(&g_easum[d], t);
    }
}

__global__ void k_loopea(const float* __restrict__ We1, const float* __restrict__ We2) {
    int j = threadIdx.x;
    float inv = 1.f / (float)N_EDGES;
    if (j < 256) {
        float s = 0.f;
        for (int d = 0; d < 32; d++) s += g_easum[d] * inv * We1[d * 256 + j];
        g_loop_ea1[j] = s;
    }
    if (j < 128) {
        float s = 0.f;
        for (int d = 0; d < 32; d++) s += g_easum[d] * inv * We2[d * 128 + j];
        g_loop_ea2[j] = s;
    }
}

/* ------------------------------------------------------------------ */
/* CSR build                                                           */
/* ------------------------------------------------------------------ */
__global__ void k_deg(const int* __restrict__ ei) {
    int e = blockIdx.x * blockDim.x + threadIdx.x;
    if (e >= EF) return;
    int dst = (e < N_EDGES) ? ei[N_EDGES + e] : (e - N_EDGES);
    atomicAdd(&g_deg[dst], 1);
}

__global__ void k_blocksum() {
    __shared__ int s[256];
    int i = blockIdx.x * 256 + threadIdx.x;
    s[threadIdx.x] = (i < N_NODES) ? g_deg[i] : 0;
    __syncthreads();
    for (int o = 128; o > 0; o >>= 1) {
        if (threadIdx.x < o) s[threadIdx.x] += s[threadIdx.x + o];
        __syncthreads();
    }
    if (threadIdx.x == 0) g_bsum[blockIdx.x] = s[0];
}

__global__ void k_scanb() {
    __shared__ int s[256];
    int t = threadIdx.x;
    int v = (t < NB_SCAN) ? g_bsum[t] : 0;
    s[t] = v;
    __syncthreads();
    for (int d = 1; d < 256; d <<= 1) {
        int x = (t >= d) ? s[t - d] : 0;
        __syncthreads();
        s[t] += x;
        __syncthreads();
    }
    g_bexcl[t] = s[t] - v;
}

__global__ void k_scanfinal() {
    __shared__ int s[256];
    int t = threadIdx.x;
    int i = blockIdx.x * 256 + t;
    int v = (i < N_NODES) ? g_deg[i] : 0;
    s[t] = v;
    __syncthreads();
    for (int d = 1; d < 256; d <<= 1) {
        int x = (t >= d) ? s[t - d] : 0;
        __syncthreads();
        s[t] += x;
        __syncthreads();
    }
    if (i < N_NODES) g_off[i] = g_bexcl[blockIdx.x] + s[t] - v;
    if (i == 0) g_off[N_NODES] = EF;
}

__global__ void k_scatter(const int* __restrict__ ei) {
    int e = blockIdx.x * blockDim.x + threadIdx.x;
    if (e >= EF) return;
    int dst, src;
    if (e < N_EDGES) { dst = ei[N_EDGES + e]; src = ei[e]; }
    else             { dst = e - N_EDGES;     src = dst; }
    int pos = atomicAdd(&g_cursor[dst], 1);
    int o = g_off[dst] + pos;
    g_eidx[o] = e;
    g_esrc[o] = src;
}

/* ------------------------------------------------------------------ */
/* tiled SGEMM  C[M,Nc] = A[M,128] @ B + bias   (fp32)                 */
/* ------------------------------------------------------------------ */
template <bool TRANSB>
__global__ void __launch_bounds__(256) k_gemm(
        const float* __restrict__ A, const float* __restrict__ B,
        const float* __restrict__ bias, float* __restrict__ C,
        int M, int Nc) {
    __shared__ float As[128][36];
    __shared__ float Bs[32][132];
    int tid = threadIdx.x;
    int tx = tid & 15, ty = tid >> 4;
    int row0 = blockIdx.y * 128;
    int col0 = blockIdx.x * 128;
    int j0 = tx * 8;
    float acc[8][8];
    #pragma unroll
    for (int i = 0; i < 8; i++)
        #pragma unroll
        for (int j = 0; j < 8; j++) acc[i][j] = 0.f;

    for (int kc = 0; kc < 4; kc++) {
        #pragma unroll
        for (int t = 0; t < 4; t++) {
            int idx4 = tid + t * 256;
            int r = idx4 >> 3, kk4 = idx4 & 7;
            float4 v = make_float4(0.f, 0.f, 0.f, 0.f);
            if (row0 + r < M)
                v = *(const float4*)(A + (size_t)(row0 + r) * 128 + kc * 32 + kk4 * 4);
            *(float4*)&As[r][kk4 * 4] = v;
        }
        if (!TRANSB) {
            #pragma unroll
            for (int t = 0; t < 4; t++) {
                int idx4 = tid + t * 256;
                int k = idx4 >> 5, c4 = idx4 & 31;
                float4 v = *(const float4*)(B + (size_t)(kc * 32 + k) * Nc + col0 + c4 * 4);
                *(float4*)&Bs[k][c4 * 4] = v;
            }
        } else {
            #pragma unroll
            for (int t = 0; t < 4; t++) {
                int idx4 = tid + t * 256;
                int j = idx4 >> 3, k4 = idx4 & 7;
                float4 v = *(const float4*)(B + (size_t)(col0 + j) * 128 + kc * 32 + k4 * 4);
                Bs[k4 * 4 + 0][j] = v.x;
                Bs[k4 * 4 + 1][j] = v.y;
                Bs[k4 * 4 + 2][j] = v.z;
                Bs[k4 * 4 + 3][j] = v.w;
            }
        }
        __syncthreads();
        #pragma unroll 8
        for (int kk = 0; kk < 32; kk++) {
            float4 b0 = *(const float4*)&Bs[kk][j0];
            float4 b1 = *(const float4*)&Bs[kk][j0 + 4];
            #pragma unroll
            for (int i = 0; i < 8; i++) {
                float a = As[ty * 8 + i][kk];
                acc[i][0] += a * b0.x; acc[i][1] += a * b0.y;
                acc[i][2] += a * b0.z; acc[i][3] += a * b0.w;
                acc[i][4] += a * b1.x; acc[i][5] += a * b1.y;
                acc[i][6] += a * b1.z; acc[i][7] += a * b1.w;
            }
        }
        __syncthreads();
    }
    float4 bv0 = *(const float4*)(bias + col0 + j0);
    float4 bv1 = *(const float4*)(bias + col0 + j0 + 4);
    #pragma unroll
    for (int i = 0; i < 8; i++) {
        int r = row0 + ty * 8 + i;
        if (r < M) {
            float4 o0, o1;
            o0.x = acc[i][0] + bv0.x; o0.y = acc[i][1] + bv0.y;
            o0.z = acc[i][2] + bv0.z; o0.w = acc[i][3] + bv0.w;
            o1.x = acc[i][4] + bv1.x; o1.y = acc[i][5] + bv1.y;
            o1.z = acc[i][6] + bv1.z; o1.w = acc[i][7] + bv1.w;
            *(float4*)(C + (size_t)r * Nc + col0 + j0) = o0;
            *(float4*)(C + (size_t)r * Nc + col0 + j0 + 4) = o1;
        }
    }
}

/* ------------------------------------------------------------------ */
/* layer-1 logits, fused tf32-mma: block = 64 edges                    */
/* sW stride 264 (bank-conflict-free B reads), sEV stride 260          */
/* smem: sW [32][264] 33792 | sA [64][36] 9216 | sEV [64][260] 66560   */
/* ------------------------------------------------------------------ */
#define L1_SMEM_BYTES 109568

__global__ void __launch_bounds__(256) k_logit_mma_l1(
        const int* __restrict__ ei, const float* __restrict__ edge_attr,
        const float* __restrict__ We, const float* __restrict__ att) {
    extern __shared__ char smem[];
    uint32_t* sW  = (uint32_t*)(smem);            /* [32][264] tf32 */
    uint32_t* sA  = (uint32_t*)(smem + 33792);    /* [64][36]  tf32 */
    float*    sEV = (float*)(smem + 43008);       /* [64][260] fp32 */

    int tid = threadIdx.x;
    int e0 = blockIdx.x * 64;

    /* phase A: We1 (32x256) + ea tile (64x32), converted to tf32 */
    #pragma unroll
    for (int t = 0; t < 8; t++) {
        int idx4 = tid + t * 256;
        int k = idx4 >> 6, c4 = idx4 & 63;
        float4 v = *(const float4*)(We + k * 256 + c4 * 4);
        uint4 u = make_uint4(f2tf(v.x), f2tf(v.y), f2tf(v.z), f2tf(v.w));
        *(uint4*)(sW + k * 264 + c4 * 4) = u;
    }
    #pragma unroll
    for (int t = 0; t < 2; t++) {
        int idx4 = tid + t * 256;
        int row = idx4 >> 3, kk4 = idx4 & 7;
        int ge = e0 + row; if (ge >= N_EDGES) ge = N_EDGES - 1;
        float4 v = *(const float4*)(edge_attr + (size_t)ge * 32 + kk4 * 4);
        uint4 u = make_uint4(f2tf(v.x), f2tf(v.y), f2tf(v.z), f2tf(v.w));
        *(uint4*)(sA + row * 36 + kk4 * 4) = u;
    }
    __syncthreads();

    int lane = tid & 31, w = tid >> 5;
    int g = lane >> 2, tig = lane & 3;
    int mt = w & 3, nh = w >> 2;
    int r0 = mt * 16 + g;
    int nb = nh * 128;

    /* phase B: M64 x N256 x K32 mma */
    float acc[16][4];
    #pragma unroll
    for (int t = 0; t < 16; t++)
        #pragma unroll
        for (int q = 0; q < 4; q++) acc[t][q] = 0.f;

    #pragma unroll
    for (int ks = 0; ks < 4; ks++) {
        int k0 = ks * 8;
        uint32_t a0 = sA[r0 * 36 + k0 + tig];
        uint32_t a1 = sA[(r0 + 8) * 36 + k0 + tig];
        uint32_t a2 = sA[r0 * 36 + k0 + tig + 4];
        uint32_t a3 = sA[(r0 + 8) * 36 + k0 + tig + 4];
        #pragma unroll
        for (int t = 0; t < 16; t++) {
            uint32_t b0 = sW[(k0 + tig) * 264 + nb + t * 8 + g];
            uint32_t b1 = sW[(k0 + tig + 4) * 264 + nb + t * 8 + g];
            mma_tf32(acc[t], a0, a1, a2, a3, b0, b1);
        }
    }
    #pragma unroll
    for (int t = 0; t < 16; t++) {
        int c = nb + t * 8 + tig * 2;
        sEV[r0 * 260 + c]           = acc[t][0];
        sEV[r0 * 260 + c + 1]       = acc[t][1];
        sEV[(r0 + 8) * 260 + c]     = acc[t][2];
        sEV[(r0 + 8) * 260 + c + 1] = acc[t][3];
    }
    __syncthreads();

    /* phase C: warp w -> edges e0 + w*8 .. +7, both heads */
    int c0 = lane * 8;
    const float4* ap = (const float4*)(att + c0);
    float4 at0 = ap[0], at1 = ap[1];
    #pragma unroll
    for (int j = 0; j < 8; j++) {
        int le = w * 8 + j;
        int e = e0 + le;
        int ce = (e < N_EDGES) ? e : N_EDGES - 1;
        int src = ei[ce];
        int dst = ei[N_EDGES + ce];
        const float4* xlp = (const float4*)(g_xl + (size_t)src * 256 + c0);
        const float4* xrp = (const float4*)(g_xr + (size_t)dst * 256 + c0);
        const float4* evp = (const float4*)(sEV + le * 260 + c0);
        float4 ev0 = evp[0], ev1 = evp[1];
        float s = 0.f, m;
        {
            float4 a = xlp[0], b = xrp[0];
            m = a.x + b.x + ev0.x; m = (m > 0.f) ? m : 0.2f * m; s += m * at0.x;
            m = a.y + b.y + ev0.y; m = (m > 0.f) ? m : 0.2f * m; s += m * at0.y;
            m = a.z + b.z + ev0.z; m = (m > 0.f) ? m : 0.2f * m; s += m * at0.z;
            m = a.w + b.w + ev0.w; m = (m > 0.f) ? m : 0.2f * m; s += m * at0.w;
        }
        {
            float4 a = xlp[1], b = xrp[1];
            m = a.x + b.x + ev1.x; m = (m > 0.f) ? m : 0.2f * m; s += m * at1.x;
            m = a.y + b.y + ev1.y; m = (m > 0.f) ? m : 0.2f * m; s += m * at1.y;
            m = a.z + b.z + ev1.z; m = (m > 0.f) ? m : 0.2f * m; s += m * at1.z;
            m = a.w + b.w + ev1.w; m = (m > 0.f) ? m : 0.2f * m; s += m * at1.w;
        }
        #pragma unroll
        for (int o = 8; o > 0; o >>= 1) s += __shfl_xor_sync(0xffffffffu, s, o);
        if ((lane & 15) == 0 && e < N_EDGES)
            g_logit[(size_t)e * 2 + (lane >> 4)] = s;
    }
}

/* ------------------------------------------------------------------ */
/* layer-2 logits, fused tf32-mma: block = 64 edges, N=128             */
/* sW stride 136, sEV stride 132                                       */
/* smem: sW [32][136] 17408 | sA [64][36] 9216 | sEV [64][132] 33792   */
/* ------------------------------------------------------------------ */
#define L2_SMEM_BYTES 60416

__global__ void __launch_bounds__(256) k_logit_mma_l2(
        const int* __restrict__ ei, const float* __restrict__ edge_attr,
        const float* __restrict__ We, const float* __restrict__ att) {
    extern __shared__ char smem[];
    uint32_t* sW  = (uint32_t*)(smem);            /* [32][136] tf32 */
    uint32_t* sA  = (uint32_t*)(smem + 17408);    /* [64][36]  tf32 */
    float*    sEV = (float*)(smem + 26624);       /* [64][132] fp32 */

    int tid = threadIdx.x;
    int e0 = blockIdx.x * 64;

    #pragma unroll
    for (int t = 0; t < 4; t++) {
        int idx4 = tid + t * 256;
        int k = idx4 >> 5, c4 = idx4 & 31;
        float4 v = *(const float4*)(We + k * 128 + c4 * 4);
        uint4 u = make_uint4(f2tf(v.x), f2tf(v.y), f2tf(v.z), f2tf(v.w));
        *(uint4*)(sW + k * 136 + c4 * 4) = u;
    }
    #pragma unroll
    for (int t = 0; t < 2; t++) {
        int idx4 = tid + t * 256;
        int row = idx4 >> 3, kk4 = idx4 & 7;
        int ge = e0 + row; if (ge >= N_EDGES) ge = N_EDGES - 1;
        float4 v = *(const float4*)(edge_attr + (size_t)ge * 32 + kk4 * 4);
        uint4 u = make_uint4(f2tf(v.x), f2tf(v.y), f2tf(v.z), f2tf(v.w));
        *(uint4*)(sA + row * 36 + kk4 * 4) = u;
    }
    __syncthreads();

    int lane = tid & 31, w = tid >> 5;
    int g = lane >> 2, tig = lane & 3;
    int mt = w & 3, nh = w >> 2;
    int r0 = mt * 16 + g;
    int nb = nh * 64;

    float acc[8][4];
    #pragma unroll
    for (int t = 0; t < 8; t++)
        #pragma unroll
        for (int q = 0; q < 4; q++) acc[t][q] = 0.f;

    #pragma unroll
    for (int ks = 0; ks < 4; ks++) {
        int k0 = ks * 8;
        uint32_t a0 = sA[r0 * 36 + k0 + tig];
        uint32_t a1 = sA[(r0 + 8) * 36 + k0 + tig];
        uint32_t a2 = sA[r0 * 36 + k0 + tig + 4];
        uint32_t a3 = sA[(r0 + 8) * 36 + k0 + tig + 4];
        #pragma unroll
        for (int t = 0; t < 8; t++) {
            uint32_t b0 = sW[(k0 + tig) * 136 + nb + t * 8 + g];
            uint32_t b1 = sW[(k0 + tig + 4) * 136 + nb + t * 8 + g];
            mma_tf32(acc[t], a0, a1, a2, a3, b0, b1);
        }
    }
    #pragma unroll
    for (int t = 0; t < 8; t++) {
        int c = nb + t * 8 + tig * 2;
        sEV[r0 * 132 + c]           = acc[t][0];
        sEV[r0 * 132 + c + 1]       = acc[t][1];
        sEV[(r0 + 8) * 132 + c]     = acc[t][2];
        sEV[(r0 + 8) * 132 + c + 1] = acc[t][3];
    }
    __syncthreads();

    int c0 = lane * 4;
    float4 at = *(const float4*)(att + c0);
    #pragma unroll
    for (int j = 0; j < 8; j++) {
        int le = w * 8 + j;
        int e = e0 + le;
        int ce = (e < N_EDGES) ? e : N_EDGES - 1;
        int src = ei[ce];
        int dst = ei[N_EDGES + ce];
        float4 a = *(const float4*)(g_xl + (size_t)src * 128 + c0);
        float4 b = *(const float4*)(g_xr + (size_t)dst * 128 + c0);
        float4 ev = *(const float4*)(sEV + le * 132 + c0);
        float s = 0.f, m;
        m = a.x + b.x + ev.x; m = (m > 0.f) ? m : 0.2f * m; s += m * at.x;
        m = a.y + b.y + ev.y; m = (m > 0.f) ? m : 0.2f * m; s += m * at.y;
        m = a.z + b.z + ev.z; m = (m > 0.f) ? m : 0.2f * m; s += m * at.z;
        m = a.w + b.w + ev.w; m = (m > 0.f) ? m : 0.2f * m; s += m * at.w;
        #pragma unroll
        for (int o = 16; o > 0; o >>= 1) s += __shfl_xor_sync(0xffffffffu, s, o);
        if (lane == 0 && e < N_EDGES)
            g_logit[e] = s;
    }
}

/* self-loop logits: warp per node, no lmax */
template <int H>
__global__ void k_logit_self(const float* __restrict__ att,
                             const float* __restrict__ loop_ea) {
    const int HC = H * 128;
    const int CPL = HC / 32;
    int n = (blockIdx.x * blockDim.x + threadIdx.x) >> 5;
    if (n >= N_NODES) return;
    int lane = threadIdx.x & 31;
    int c0 = lane * CPL;
    const float4* xlp = (const float4*)(g_xl + (size_t)n * HC + c0);
    const float4* xrp = (const float4*)(g_xr + (size_t)n * HC + c0);
    const float4* lp  = (const float4*)(loop_ea + c0);
    const float4* ap  = (const float4*)(att + c0);
    float s = 0.f;
    #pragma unroll
    for (int q4 = 0; q4 < CPL / 4; q4++) {
        float4 a = xlp[q4], b = xrp[q4], e = lp[q4], at = ap[q4];
        float m;
        m = a.x + b.x + e.x; m = (m > 0.f) ? m : 0.2f * m; s += m * at.x;
        m = a.y + b.y + e.y; m = (m > 0.f) ? m : 0.2f * m; s += m * at.y;
        m = a.z + b.z + e.z; m = (m > 0.f) ? m : 0.2f * m; s += m * at.z;
        m = a.w + b.w + e.w; m = (m > 0.f) ? m : 0.2f * m; s += m * at.w;
    }
    if (H == 2) {
        #pragma unroll
        for (int o = 8; o > 0; o >>= 1) s += __shfl_xor_sync(0xffffffffu, s, o);
        if ((lane & 15) == 0) {
            int h = lane >> 4;
            g_logit[(size_t)(N_EDGES + n) * 2 + h] = s;
        }
    } else {
        #pragma unroll
        for (int o = 16; o > 0; o >>= 1) s += __shfl_xor_sync(0xffffffffu, s, o);
        if (lane == 0)
            g_logit[N_EDGES + n] = s;
    }
}

/* ------------------------------------------------------------------ */
/* aggregation, fused softmax (no lmax): warp per dst node, CSR        */
/* uses g_esrc (no dependent ei[g_eidx[.]] chain)                      */
/* ------------------------------------------------------------------ */
template <int H>
__global__ void k_agg(const float* __restrict__ bias, float* __restrict__ z) {
    const int HC = H * 128;
    const int CPL = HC / 32;
    int n = (blockIdx.x * blockDim.x + threadIdx.x) >> 5;
    if (n >= N_NODES) return;
    int lane = threadIdx.x & 31;
    int c0 = lane * CPL;
    int h = (H == 2) ? (lane >> 4) : 0;
    float sum_p = 0.f;
    float acc[8];
    #pragma unroll
    for (int q = 0; q < CPL; q++) acc[q] = 0.f;
    int b0 = g_off[n], b1 = g_off[n + 1];
    for (int idx = b0; idx < b1; idx++) {
        int e = g_eidx[idx];
        int src = g_esrc[idx];
        float p = __expf(g_logit[(size_t)e * H + h]);
        sum_p += p;
        const float4* xp = (const float4*)(g_xl + (size_t)src * HC + c0);
        #pragma unroll
        for (int q4 = 0; q4 < CPL / 4; q4++) {
            float4 v = xp[q4];
            acc[q4 * 4 + 0] += p * v.x;
            acc[q4 * 4 + 1] += p * v.y;
            acc[q4 * 4 + 2] += p * v.z;
            acc[q4 * 4 + 3] += p * v.w;
        }
    }
    float inv = 1.f / sum_p;
    #pragma unroll
    for (int q = 0; q < CPL; q++) acc[q] *= inv;
    if (H == 2) {
        #pragma unroll
        for (int q = 0; q < 8; q++)
            acc[q] = 0.5f * (acc[q] + __shfl_xor_sync(0xffffffffu, acc[q], 16));
        if (lane < 16) {
            int c = lane * 8;
            float4 o0, o1;
            float v;
            v = acc[0] + bias[c + 0]; o0.x = (v > 0.f) ? v : expm1f(v);
            v = acc[1] + bias[c + 1]; o0.y = (v > 0.f) ? v : expm1f(v);
            v = acc[2] + bias[c + 2]; o0.z = (v > 0.f) ? v : expm1f(v);
            v = acc[3] + bias[c + 3]; o0.w = (v > 0.f) ? v : expm1f(v);
            v = acc[4] + bias[c + 4]; o1.x = (v > 0.f) ? v : expm1f(v);
            v = acc[5] + bias[c + 5]; o1.y = (v > 0.f) ? v : expm1f(v);
            v = acc[6] + bias[c + 6]; o1.z = (v > 0.f) ? v : expm1f(v);
            v = acc[7] + bias[c + 7]; o1.w = (v > 0.f) ? v : expm1f(v);
            *(float4*)(z + (size_t)n * 128 + c) = o0;
            *(float4*)(z + (size_t)n * 128 + c + 4) = o1;
        }
    } else {
        int c = lane * 4;
        float4 o;
        float v;
        v = acc[0] + bias[c + 0]; o.x = (v > 0.f) ? v : expm1f(v);
        v = acc[1] + bias[c + 1]; o.y = (v > 0.f) ? v : expm1f(v);
        v = acc[2] + bias[c + 2]; o.z = (v > 0.f) ? v : expm1f(v);
        v = acc[3] + bias[c + 3]; o.w = (v > 0.f) ? v : expm1f(v);
        *(float4*)(z + (size_t)n * 128 + c) = o;
    }
}

/* ------------------------------------------------------------------ */
/* GRU (h_prev = 0): h = (1-u)*g                                       */
/* ------------------------------------------------------------------ */
__global__ void k_gru(const float* __restrict__ b_hh) {
    int i = blockIdx.x * blockDim.x + threadIdx.x;
    if (i >= N_NODES * 128) return;
    int n = i >> 7;
    int c = i & 127;
    const float* gi = g_gi + (size_t)n * 384;
    float r = 1.f / (1.f + __expf(-(gi[c] + b_hh[c])));
    float u = 1.f / (1.f + __expf(-(gi[128 + c] + b_hh[128 + c])));
    float g = tanhf(gi[256 + c] + r * b_hh[256 + c]);
    g_h[i] = (1.f - u) * g;
}

/* ------------------------------------------------------------------ */
/* fused edge classifier, tf32 tensor cores                            */
/* sBu stride 136 (bank-conflict-free B reads)                         */
/* smem: src 0 | dst 512 | sAu 1024 [128][36] | sBu 19456 [32][136]    */
/*       sh1u 36864 [128][132] | sh2 overlay 1024 [128][68]            */
/* ------------------------------------------------------------------ */
#define CLS_SMEM_BYTES 104448

__global__ void __launch_bounds__(256) k_cls(
        const int* __restrict__ ei, const float* __restrict__ edge_attr,
        const float* __restrict__ Wc1, const float* __restrict__ bc1,
        const float* __restrict__ Wc2, const float* __restrict__ bc2,
        const float* __restrict__ Wc3, const float* __restrict__ bc3,
        float* __restrict__ out) {
    extern __shared__ char smem[];
    int*      s_src = (int*)smem;
    int*      s_dst = (int*)(smem + 512);
    uint32_t* sAu   = (uint32_t*)(smem + 1024);    /* [128][36]  tf32 */
    uint32_t* sBu   = (uint32_t*)(smem + 19456);   /* [32][136]  tf32 */
    uint32_t* sh1u  = (uint32_t*)(smem + 36864);   /* [128][132] tf32 */
    float*    sh2   = (float*)(smem + 1024);       /* [128][68] fp32 overlay */

    int tid = threadIdx.x;
    int e0 = blockIdx.x * 128;
    {
        int ge = e0 + (tid & 127);
        if (ge >= N_EDGES) ge = N_EDGES - 1;
        if (tid < 128) s_src[tid] = ei[ge];
        else           s_dst[tid - 128] = ei[N_EDGES + ge];
    }
    __syncthreads();

    int lane = tid & 31, w = tid >> 5;
    int g = lane >> 2, tig = lane & 3;
    int r0 = w * 16 + g;

    float acc[16][4];
    #pragma unroll
    for (int t = 0; t < 16; t++)
        #pragma unroll
        for (int q = 0; q < 4; q++) acc[t][q] = 0.f;

    for (int kc = 0; kc < 9; kc++) {
        #pragma unroll
        for (int t = 0; t < 4; t++) {
            int idx4 = tid + t * 256;
            int row = idx4 >> 3, kk4 = idx4 & 7;
            int k0 = kc * 32 + kk4 * 4;
            float4 v;
            if (kc < 4)
                v = *(const float4*)(g_h + (size_t)s_src[row] * 128 + k0);
            else if (kc < 8)
                v = *(const float4*)(g_h + (size_t)s_dst[row] * 128 + (k0 - 128));
            else {
                int ge = e0 + row; if (ge >= N_EDGES) ge = N_EDGES - 1;
                v = *(const float4*)(edge_attr + (size_t)ge * 32 + (k0 - 256));
            }
            uint4 u = make_uint4(f2tf(v.x), f2tf(v.y), f2tf(v.z), f2tf(v.w));
            *(uint4*)(sAu + row * 36 + kk4 * 4) = u;
        }
        #pragma unroll
        for (int t = 0; t < 4; t++) {
            int idx4 = tid + t * 256;
            int k = idx4 >> 5, c4 = idx4 & 31;
            float4 v = *(const float4*)(Wc1 + (size_t)(kc * 32 + k) * 128 + c4 * 4);
            uint4 u = make_uint4(f2tf(v.x), f2tf(v.y), f2tf(v.z), f2tf(v.w));
            *(uint4*)(sBu + k * 136 + c4 * 4) = u;
        }
        __syncthreads();
        #pragma unroll
        for (int ks = 0; ks < 4; ks++) {
            int k0 = ks * 8;
            uint32_t a0 = sAu[r0 * 36 + k0 + tig];
            uint32_t a1 = sAu[(r0 + 8) * 36 + k0 + tig];
            uint32_t a2 = sAu[r0 * 36 + k0 + tig + 4];
            uint32_t a3 = sAu[(r0 + 8) * 36 + k0 + tig + 4];
            #pragma unroll
            for (int t = 0; t < 16; t++) {
                uint32_t b0 = sBu[(k0 + tig) * 136 + t * 8 + g];
                uint32_t b1 = sBu[(k0 + tig + 4) * 136 + t * 8 + g];
                mma_tf32(acc[t], a0, a1, a2, a3, b0, b1);
            }
        }
        __syncthreads();
    }
    #pragma unroll
    for (int t = 0; t < 16; t++) {
        int c = t * 8 + tig * 2;
        float bb0 = bc1[c], bb1 = bc1[c + 1];
        sh1u[r0 * 132 + c]           = f2tf(fmaxf(acc[t][0] + bb0, 0.f));
        sh1u[r0 * 132 + c + 1]       = f2tf(fmaxf(acc[t][1] + bb1, 0.f));
        sh1u[(r0 + 8) * 132 + c]     = f2tf(fmaxf(acc[t][2] + bb0, 0.f));
        sh1u[(r0 + 8) * 132 + c + 1] = f2tf(fmaxf(acc[t][3] + bb1, 0.f));
    }
    __syncthreads();

    float acc2[8][4];
    #pragma unroll
    for (int t = 0; t < 8; t++)
        #pragma unroll
        for (int q = 0; q < 4; q++) acc2[t][q] = 0.f;

    for (int kc = 0; kc < 4; kc++) {
        #pragma unroll
        for (int t = 0; t < 2; t++) {
            int idx4 = tid + t * 256;
            int k = idx4 >> 4, c4 = idx4 & 15;
            float4 v = *(const float4*)(Wc2 + (size_t)(kc * 32 + k) * 64 + c4 * 4);
            uint4 u = make_uint4(f2tf(v.x), f2tf(v.y), f2tf(v.z), f2tf(v.w));
            *(uint4*)(sBu + k * 136 + c4 * 4) = u;
        }
        __syncthreads();
        #pragma unroll
        for (int ks = 0; ks < 4; ks++) {
            int kk = kc * 32 + ks * 8;
            uint32_t a0 = sh1u[r0 * 132 + kk + tig];
            uint32_t a1 = sh1u[(r0 + 8) * 132 + kk + tig];
            uint32_t a2 = sh1u[r0 * 132 + kk + tig + 4];
            uint32_t a3 = sh1u[(r0 + 8) * 132 + kk + tig + 4];
            #pragma unroll
            for (int t = 0; t < 8; t++) {
                uint32_t b0 = sBu[(ks * 8 + tig) * 136 + t * 8 + g];
                uint32_t b1 = sBu[(ks * 8 + tig + 4) * 136 + t * 8 + g];
                mma_tf32(acc2[t], a0, a1, a2, a3, b0, b1);
            }
        }
        __syncthreads();
    }
    #pragma unroll
    for (int t = 0; t < 8; t++) {
        int c = t * 8 + tig * 2;
        float bb0 = bc2[c], bb1 = bc2[c + 1];
        sh2[r0 * 68 + c]           = fmaxf(acc2[t][0] + bb0, 0.f);
        sh2[r0 * 68 + c + 1]       = fmaxf(acc2[t][1] + bb1, 0.f);
        sh2[(r0 + 8) * 68 + c]     = fmaxf(acc2[t][2] + bb0, 0.f);
        sh2[(r0 + 8) * 68 + c + 1] = fmaxf(acc2[t][3] + bb1, 0.f);
    }
    __syncthreads();

    {
        int e = tid >> 1;
        int o = tid & 1;
        float s = bc3[o];
        const float* hr = sh2 + e * 68;
        #pragma unroll 8
        for (int k = 0; k < 64; k++) s += hr[k] * Wc3[k * 2 + o];
        int ge = e0 + e;
        if (ge < N_EDGES) out[(size_t)ge * 2 + o] = s;
    }
}

/* ------------------------------------------------------------------ */
/* launch: dual-stream overlap, mma logits                             */
/* ------------------------------------------------------------------ */
extern "C" void kernel_launch(void* const* d_in, const int* in_sizes, int n_in,
                              void* d_out, int out_size) {
    (void)in_sizes; (void)n_in; (void)out_size;
    const float* x     = (const float*)d_in[0];
    const int*   ei    = (const int*)d_in[1];
    const float* ea    = (const float*)d_in[2];
    /* d_in[3] global_ids unused */
    const float* Wl1 = (const float*)d_in[4];
    const float* bl1 = (const float*)d_in[5];
    const float* Wr1 = (const float*)d_in[6];
    const float* br1 = (const float*)d_in[7];
    const float* We1 = (const float*)d_in[8];
    const float* att1 = (const float*)d_in[9];
    const float* bias1 = (const float*)d_in[10];
    const float* Wl2 = (const float*)d_in[11];
    const float* bl2 = (const float*)d_in[12];
    const float* Wr2 = (const float*)d_in[13];
    const float* br2 = (const float*)d_in[14];
    const float* We2 = (const float*)d_in[15];
    const float* att2 = (const float*)d_in[16];
    const float* bias2 = (const float*)d_in[17];
    const float* W_ih = (const float*)d_in[18];
    /* d_in[19] W_hh unused: h_prev == 0 */
    const float* b_ih = (const float*)d_in[20];
    const float* b_hh = (const float*)d_in[21];
    const float* Wc1 = (const float*)d_in[22];
    const float* bc1 = (const float*)d_in[23];
    const float* Wc2 = (const float*)d_in[24];
    const float* bc2 = (const float*)d_in[25];
    const float* Wc3 = (const float*)d_in[26];
    const float* bc3 = (const float*)d_in[27];
    float* out = (float*)d_out;

    float *p_xl, *p_xr, *p_z1, *p_z2, *p_gi, *p_lea1, *p_lea2;
    cudaGetSymbolAddress((void**)&p_xl, g_xl);
    cudaGetSymbolAddress((void**)&p_xr, g_xr);
    cudaGetSymbolAddress((void**)&p_z1, g_z1);
    cudaGetSymbolAddress((void**)&p_z2, g_z2);
    cudaGetSymbolAddress((void**)&p_gi, g_gi);
    cudaGetSymbolAddress((void**)&p_lea1, g_loop_ea1);
    cudaGetSymbolAddress((void**)&p_lea2, g_loop_ea2);

    /* one-time setup (first call is the uncaptured correctness run) */
    static int setup_done = 0;
    static cudaStream_t s2;
    static cudaEvent_t ev0, evL, evCSR, evAgg1, evX2;
    if (!setup_done) {
        cudaFuncSetAttribute(k_cls, cudaFuncAttributeMaxDynamicSharedMemorySize,
                             CLS_SMEM_BYTES);
        cudaFuncSetAttribute(k_logit_mma_l1, cudaFuncAttributeMaxDynamicSharedMemorySize,
                             L1_SMEM_BYTES);
        cudaFuncSetAttribute(k_logit_mma_l2, cudaFuncAttributeMaxDynamicSharedMemorySize,
                             L2_SMEM_BYTES);
        cudaStreamCreateWithFlags(&s2, cudaStreamNonBlocking);
        cudaEventCreateWithFlags(&ev0,   cudaEventDisableTiming);
        cudaEventCreateWithFlags(&evL,   cudaEventDisableTiming);
        cudaEventCreateWithFlags(&evCSR, cudaEventDisableTiming);
        cudaEventCreateWithFlags(&evAgg1, cudaEventDisableTiming);
        cudaEventCreateWithFlags(&evX2,  cudaEventDisableTiming);
        setup_done = 1;
    }

    dim3 tb(256);
    int gy = (N_NODES + 127) / 128;
    int logit_blocks = (N_EDGES + 63) / 64;

    /* main: init, then the layer-1 GEMM+logit chain (logit_mma_l1 = 4th launch) */
    k_init<<<(N_NODES + 255) / 256, 256>>>();
    cudaEventRecord(ev0, 0);
    k_gemm<false><<<dim3(2, gy), tb>>>(x, Wl1, bl1, p_xl, N_NODES, 256);
    k_gemm<false><<<dim3(2, gy), tb>>>(x, Wr1, br1, p_xr, N_NODES, 256);
    k_logit_mma_l1<<<logit_blocks, 256, L1_SMEM_BYTES>>>(ei, ea, We1, att1);

    /* side stream: easum/loopea + CSR build, forked after k_init */
    cudaStreamWaitEvent(s2, ev0, 0);
    k_easum<<<(N_EDGES + 1023) / 1024, 256, 0, s2>>>(ea);
    k_loopea<<<1, 256, 0, s2>>>(We1, We2);
    cudaEventRecord(evL, s2);
    k_deg<<<(EF + 255) / 256, 256, 0, s2>>>(ei);
    k_blocksum<<<NB_SCAN, 256, 0, s2>>>();
    k_scanb<<<1, 256, 0, s2>>>();
    k_scanfinal<<<NB_SCAN, 256, 0, s2>>>();
    k_scatter<<<(EF + 255) / 256, 256, 0, s2>>>(ei);
    cudaEventRecord(evCSR, s2);

    /* main: self-loop logits need loopea; agg needs CSR */
    cudaStreamWaitEvent(0, evL, 0);
    k_logit_self<2><<<(N_NODES + 7) / 8, 256>>>(att1, p_lea1);
    cudaStreamWaitEvent(0, evCSR, 0);
    k_agg<2><<<(N_NODES + 7) / 8, 256>>>(bias1, p_z1);
    cudaEventRecord(evAgg1, 0);

    /* layer 2: xl2 on main, xr2 concurrent on s2 */
    cudaStreamWaitEvent(s2, evAgg1, 0);
    k_gemm<false><<<dim3(1, gy), tb, 0, s2>>>(p_z1, Wr2, br2, p_xr, N_NODES, 128);
    cudaEventRecord(evX2, s2);
    k_gemm<false><<<dim3(1, gy), tb>>>(p_z1, Wl2, bl2, p_xl, N_NODES, 128);
    cudaStreamWaitEvent(0, evX2, 0);
    k_logit_mma_l2<<<logit_blocks, 256, L2_SMEM_BYTES>>>(ei, ea, We2, att2);
    k_logit_self<1><<<(N_NODES + 7) / 8, 256>>>(att2, p_lea2);
    k_agg<1><<<(N_NODES + 7) / 8, 256>>>(bias2, p_z2);

    /* GRU (h_prev = 0) */
    k_gemm<true><<<dim3(3, gy), tb>>>(p_z2, W_ih, b_ih, p_gi, N_NODES, 384);
    k_gru<<<(N_NODES * 128 + 255) / 256, 256>>>(b_hh);

    /* edge classifier (tf32 tensor cores) */
    k_cls<<<(N_EDGES + 127) / 128, 256, CLS_SMEM_BYTES>>>(
        ei, ea, Wc1, bc1, Wc2, bc2, Wc3, bc3, out);
}

// round 16
// speedup vs baseline: 1.2403x; 1.0210x over previous
#include <cuda_runtime.h>
#include <math.h>
#include <stdint.h>

#define N_NODES 50000
#define N_EDGES 500000
#define EF (N_EDGES + N_NODES)  /* 550000 */
#define NB_SCAN 196             /* ceil(N_NODES/256) */

/* ------------------------------------------------------------------ */
/* scratch (static device memory; no runtime allocation allowed)       */
/* ------------------------------------------------------------------ */
__device__ float g_xl[N_NODES * 256];
__device__ float g_xr[N_NODES * 256];
__device__ float g_z1[N_NODES * 128];
__device__ float g_z2[N_NODES * 128];
__device__ float g_h [N_NODES * 128];
__device__ float g_logit[EF * 2];
__device__ int   g_deg[N_NODES];
__device__ int   g_cursor[N_NODES];
__device__ int   g_off[N_NODES + 1];
__device__ int   g_eidx[EF];
__device__ int   g_esrc[EF];
__device__ float g_easum[32];
__device__ float g_loop_ea1[256];
__device__ float g_loop_ea2[128];
__device__ int   g_bsum[256];
__device__ int   g_bexcl[256];

/* ------------------------------------------------------------------ */
__device__ __forceinline__ uint32_t f2tf(float f) {
    uint32_t u;
    asm("cvt.rna.tf32.f32 %0, %1;" : "=r"(u) : "f"(f));
    return u;
}

__device__ __forceinline__ void mma_tf32(float* c,
        uint32_t a0, uint32_t a1, uint32_t a2, uint32_t a3,
        uint32_t b0, uint32_t b1) {
    asm volatile(
        "mma.sync.aligned.m16n8k8.row.col.f32.tf32.tf32.f32 "
        "{%0,%1,%2,%3}, {%4,%5,%6,%7}, {%8,%9}, {%0,%1,%2,%3};"
        : "+f"(c[0]), "+f"(c[1]), "+f"(c[2]), "+f"(c[3])
        : "r"(a0), "r"(a1), "r"(a2), "r"(a3), "r"(b0), "r"(b1));
}

/* ------------------------------------------------------------------ */
/* init / edge_attr mean / loop edge features                          */
/* ------------------------------------------------------------------ */
__global__ void k_init() {
    int i = blockIdx.x * blockDim.x + threadIdx.x;
    if (i < N_NODES) { g_deg[i] = 0; g_cursor[i] = 0; }
    if (i < 32) g_easum[i] = 0.f;
}

__global__ void k_easum(const float* __restrict__ ea) {
    __shared__ float s[8][32];
    int d = threadIdx.x & 31;
    int r = threadIdx.x >> 5;
    int base = blockIdx.x * 1024;
    int end  = base + 1024; if (end > N_EDGES) end = N_EDGES;
    float acc = 0.f;
    for (int e = base + r; e < end; e += 8)
        acc += ea[(size_t)e * 32 + d];
    s[r][d] = acc;
    __syncthreads();
    if (r == 0) {
        float t = 0.f;
        #pragma unroll
        for (int i = 0; i < 8; i++) t += s[i][d];
        atomicAdd(&g_easum[d], t);
    }
}

__global__ void k_loopea(const float* __restrict__ We1, const float* __restrict__ We2) {
    int j = threadIdx.x;
    float inv = 1.f / (float)N_EDGES;
    if (j < 256) {
        float s = 0.f;
        for (int d = 0; d < 32; d++) s += g_easum[d] * inv * We1[d * 256 + j];
        g_loop_ea1[j] = s;
    }
    if (j < 128) {
        float s = 0.f;
        for (int d = 0; d < 32; d++) s += g_easum[d] * inv * We2[d * 128 + j];
        g_loop_ea2[j] = s;
    }
}

/* ------------------------------------------------------------------ */
/* CSR build                                                           */
/* ------------------------------------------------------------------ */
__global__ void k_deg(const int* __restrict__ ei) {
    int e = blockIdx.x * blockDim.x + threadIdx.x;
    if (e >= EF) return;
    int dst = (e < N_EDGES) ? ei[N_EDGES + e] : (e - N_EDGES);
    atomicAdd(&g_deg[dst], 1);
}

__global__ void k_blocksum() {
    __shared__ int s[256];
    int i = blockIdx.x * 256 + threadIdx.x;
    s[threadIdx.x] = (i < N_NODES) ? g_deg[i] : 0;
    __syncthreads();
    for (int o = 128; o > 0; o >>= 1) {
        if (threadIdx.x < o) s[threadIdx.x] += s[threadIdx.x + o];
        __syncthreads();
    }
    if (threadIdx.x == 0) g_bsum[blockIdx.x] = s[0];
}

__global__ void k_scanb() {
    __shared__ int s[256];
    int t = threadIdx.x;
    int v = (t < NB_SCAN) ? g_bsum[t] : 0;
    s[t] = v;
    __syncthreads();
    for (int d = 1; d < 256; d <<= 1) {
        int x = (t >= d) ? s[t - d] : 0;
        __syncthreads();
        s[t] += x;
        __syncthreads();
    }
    g_bexcl[t] = s[t] - v;
}

__global__ void k_scanfinal() {
    __shared__ int s[256];
    int t = threadIdx.x;
    int i = blockIdx.x * 256 + t;
    int v = (i < N_NODES) ? g_deg[i] : 0;
    s[t] = v;
    __syncthreads();
    for (int d = 1; d < 256; d <<= 1) {
        int x = (t >= d) ? s[t - d] : 0;
        __syncthreads();
        s[t] += x;
        __syncthreads();
    }
    if (i < N_NODES) g_off[i] = g_bexcl[blockIdx.x] + s[t] - v;
    if (i == 0) g_off[N_NODES] = EF;
}

__global__ void k_scatter(const int* __restrict__ ei) {
    int e = blockIdx.x * blockDim.x + threadIdx.x;
    if (e >= EF) return;
    int dst, src;
    if (e < N_EDGES) { dst = ei[N_EDGES + e]; src = ei[e]; }
    else             { dst = e - N_EDGES;     src = dst; }
    int pos = atomicAdd(&g_cursor[dst], 1);
    int o = g_off[dst] + pos;
    g_eidx[o] = e;
    g_esrc[o] = src;
}

/* ------------------------------------------------------------------ */
/* tiled SGEMM  C[M,Nc] = A[M,128] @ B + bias   (fp32, B row-major)    */
/* ------------------------------------------------------------------ */
__global__ void __launch_bounds__(256) k_gemm(
        const float* __restrict__ A, const float* __restrict__ B,
        const float* __restrict__ bias, float* __restrict__ C,
        int M, int Nc) {
    __shared__ float As[128][36];
    __shared__ float Bs[32][132];
    int tid = threadIdx.x;
    int tx = tid & 15, ty = tid >> 4;
    int row0 = blockIdx.y * 128;
    int col0 = blockIdx.x * 128;
    int j0 = tx * 8;
    float acc[8][8];
    #pragma unroll
    for (int i = 0; i < 8; i++)
        #pragma unroll
        for (int j = 0; j < 8; j++) acc[i][j] = 0.f;

    for (int kc = 0; kc < 4; kc++) {
        #pragma unroll
        for (int t = 0; t < 4; t++) {
            int idx4 = tid + t * 256;
            int r = idx4 >> 3, kk4 = idx4 & 7;
            float4 v = make_float4(0.f, 0.f, 0.f, 0.f);
            if (row0 + r < M)
                v = *(const float4*)(A + (size_t)(row0 + r) * 128 + kc * 32 + kk4 * 4);
            *(float4*)&As[r][kk4 * 4] = v;
        }
        #pragma unroll
        for (int t = 0; t < 4; t++) {
            int idx4 = tid + t * 256;
            int k = idx4 >> 5, c4 = idx4 & 31;
            float4 v = *(const float4*)(B + (size_t)(kc * 32 + k) * Nc + col0 + c4 * 4);
            *(float4*)&Bs[k][c4 * 4] = v;
        }
        __syncthreads();
        #pragma unroll 8
        for (int kk = 0; kk < 32; kk++) {
            float4 b0 = *(const float4*)&Bs[kk][j0];
            float4 b1 = *(const float4*)&Bs[kk][j0 + 4];
            #pragma unroll
            for (int i = 0; i < 8; i++) {
                float a = As[ty * 8 + i][kk];
                acc[i][0] += a * b0.x; acc[i][1] += a * b0.y;
                acc[i][2] += a * b0.z; acc[i][3] += a * b0.w;
                acc[i][4] += a * b1.x; acc[i][5] += a * b1.y;
                acc[i][6] += a * b1.z; acc[i][7] += a * b1.w;
            }
        }
        __syncthreads();
    }
    float4 bv0 = *(const float4*)(bias + col0 + j0);
    float4 bv1 = *(const float4*)(bias + col0 + j0 + 4);
    #pragma unroll
    for (int i = 0; i < 8; i++) {
        int r = row0 + ty * 8 + i;
        if (r < M) {
            float4 o0, o1;
            o0.x = acc[i][0] + bv0.x; o0.y = acc[i][1] + bv0.y;
            o0.z = acc[i][2] + bv0.z; o0.w = acc[i][3] + bv0.w;
            o1.x = acc[i][4] + bv1.x; o1.y = acc[i][5] + bv1.y;
            o1.z = acc[i][6] + bv1.z; o1.w = acc[i][7] + bv1.w;
            *(float4*)(C + (size_t)r * Nc + col0 + j0) = o0;
            *(float4*)(C + (size_t)r * Nc + col0 + j0 + 4) = o1;
        }
    }
}

/* ------------------------------------------------------------------ */
/* fused GRU GEMM: h = (1-u)*g from z2 @ W_ih^T, no g_gi roundtrip     */
/* block = 64 rows x 64 output cols, 3 gate dots per output            */
/* ------------------------------------------------------------------ */
__global__ void __launch_bounds__(256) k_gru_gemm(
        const float* __restrict__ A,      /* z2 [M,128] */
        const float* __restrict__ W,      /* W_ih [384,128] row-major */
        const float* __restrict__ b_ih, const float* __restrict__ b_hh,
        float* __restrict__ Hout, int M) {
    __shared__ float As[64][36];
    __shared__ float Bs[3][32][68];
    int tid = threadIdx.x;
    int tx = tid & 15, ty = tid >> 4;
    int row0 = blockIdx.y * 64;
    int col0 = blockIdx.x * 64;
    int j0 = tx * 4;
    float acc[3][4][4];
    #pragma unroll
    for (int gq = 0; gq < 3; gq++)
        #pragma unroll
        for (int i = 0; i < 4; i++)
            #pragma unroll
            for (int j = 0; j < 4; j++) acc[gq][i][j] = 0.f;

    for (int kc = 0; kc < 4; kc++) {
        #pragma unroll
        for (int t = 0; t < 2; t++) {
            int idx4 = tid + t * 256;
            int r = idx4 >> 3, kk4 = idx4 & 7;
            float4 v = make_float4(0.f, 0.f, 0.f, 0.f);
            if (row0 + r < M)
                v = *(const float4*)(A + (size_t)(row0 + r) * 128 + kc * 32 + kk4 * 4);
            *(float4*)&As[r][kk4 * 4] = v;
        }
        #pragma unroll
        for (int t = 0; t < 6; t++) {
            int idx4 = tid + t * 256;
            int gq = idx4 >> 9;
            int r = idx4 & 511;
            int j = r >> 3, k4 = r & 7;
            float4 v = *(const float4*)(W + (size_t)(gq * 128 + col0 + j) * 128
                                          + kc * 32 + k4 * 4);
            Bs[gq][k4 * 4 + 0][j] = v.x;
            Bs[gq][k4 * 4 + 1][j] = v.y;
            Bs[gq][k4 * 4 + 2][j] = v.z;
            Bs[gq][k4 * 4 + 3][j] = v.w;
        }
        __syncthreads();
        #pragma unroll 4
        for (int kk = 0; kk < 32; kk++) {
            float a0 = As[ty * 4 + 0][kk];
            float a1 = As[ty * 4 + 1][kk];
            float a2 = As[ty * 4 + 2][kk];
            float a3 = As[ty * 4 + 3][kk];
            #pragma unroll
            for (int gq = 0; gq < 3; gq++) {
                float4 b = *(const float4*)&Bs[gq][kk][j0];
                acc[gq][0][0] += a0 * b.x; acc[gq][0][1] += a0 * b.y;
                acc[gq][0][2] += a0 * b.z; acc[gq][0][3] += a0 * b.w;
                acc[gq][1][0] += a1 * b.x; acc[gq][1][1] += a1 * b.y;
                acc[gq][1][2] += a1 * b.z; acc[gq][1][3] += a1 * b.w;
                acc[gq][2][0] += a2 * b.x; acc[gq][2][1] += a2 * b.y;
                acc[gq][2][2] += a2 * b.z; acc[gq][2][3] += a2 * b.w;
                acc[gq][3][0] += a3 * b.x; acc[gq][3][1] += a3 * b.y;
                acc[gq][3][2] += a3 * b.z; acc[gq][3][3] += a3 * b.w;
            }
        }
        __syncthreads();
    }
    #pragma unroll
    for (int i = 0; i < 4; i++) {
        int row = row0 + ty * 4 + i;
        if (row >= M) continue;
        #pragma unroll
        for (int jj = 0; jj < 4; jj++) {
            int c = col0 + j0 + jj;
            float gr = acc[0][i][jj] + b_ih[c];
            float gz = acc[1][i][jj] + b_ih[128 + c];
            float gg = acc[2][i][jj] + b_ih[256 + c];
            float r = 1.f / (1.f + __expf(-(gr + b_hh[c])));
            float u = 1.f / (1.f + __expf(-(gz + b_hh[128 + c])));
            float g = tanhf(gg + r * b_hh[256 + c]);
            Hout[(size_t)row * 128 + c] = (1.f - u) * g;
        }
    }
}

/* ------------------------------------------------------------------ */
/* layer-1 logits, fused tf32-mma: block = 64 edges                    */
/* sEV OVERLAYS sW/sA after the mma (fragments live in registers)      */
/* smem: phase A/B: sW [32][264] @0 33792 | sA [64][36] @33792 9216    */
/*       phase C:   sEV [64][260] @0 66560                             */
/* ------------------------------------------------------------------ */
#define L1_SMEM_BYTES 66560

__global__ void __launch_bounds__(256) k_logit_mma_l1(
        const int* __restrict__ ei, const float* __restrict__ edge_attr,
        const float* __restrict__ We, const float* __restrict__ att) {
    extern __shared__ char smem[];
    uint32_t* sW  = (uint32_t*)(smem);            /* [32][264] tf32 */
    uint32_t* sA  = (uint32_t*)(smem + 33792);    /* [64][36]  tf32 */
    float*    sEV = (float*)(smem);               /* [64][260] fp32 overlay */

    int tid = threadIdx.x;
    int e0 = blockIdx.x * 64;

    /* phase A: We1 (32x256) + ea tile (64x32), converted to tf32 */
    #pragma unroll
    for (int t = 0; t < 8; t++) {
        int idx4 = tid + t * 256;
        int k = idx4 >> 6, c4 = idx4 & 63;
        float4 v = *(const float4*)(We + k * 256 + c4 * 4);
        uint4 u = make_uint4(f2tf(v.x), f2tf(v.y), f2tf(v.z), f2tf(v.w));
        *(uint4*)(sW + k * 264 + c4 * 4) = u;
    }
    #pragma unroll
    for (int t = 0; t < 2; t++) {
        int idx4 = tid + t * 256;
        int row = idx4 >> 3, kk4 = idx4 & 7;
        int ge = e0 + row; if (ge >= N_EDGES) ge = N_EDGES - 1;
        float4 v = *(const float4*)(edge_attr + (size_t)ge * 32 + kk4 * 4);
        uint4 u = make_uint4(f2tf(v.x), f2tf(v.y), f2tf(v.z), f2tf(v.w));
        *(uint4*)(sA + row * 36 + kk4 * 4) = u;
    }
    __syncthreads();

    int lane = tid & 31, w = tid >> 5;
    int g = lane >> 2, tig = lane & 3;
    int mt = w & 3, nh = w >> 2;
    int r0 = mt * 16 + g;
    int nb = nh * 128;

    /* phase B: M64 x N256 x K32 mma (accumulators stay in registers) */
    float acc[16][4];
    #pragma unroll
    for (int t = 0; t < 16; t++)
        #pragma unroll
        for (int q = 0; q < 4; q++) acc[t][q] = 0.f;

    #pragma unroll
    for (int ks = 0; ks < 4; ks++) {
        int k0 = ks * 8;
        uint32_t a0 = sA[r0 * 36 + k0 + tig];
        uint32_t a1 = sA[(r0 + 8) * 36 + k0 + tig];
        uint32_t a2 = sA[r0 * 36 + k0 + tig + 4];
        uint32_t a3 = sA[(r0 + 8) * 36 + k0 + tig + 4];
        #pragma unroll
        for (int t = 0; t < 16; t++) {
            uint32_t b0 = sW[(k0 + tig) * 264 + nb + t * 8 + g];
            uint32_t b1 = sW[(k0 + tig + 4) * 264 + nb + t * 8 + g];
            mma_tf32(acc[t], a0, a1, a2, a3, b0, b1);
        }
    }
    __syncthreads();   /* all reads of sW/sA done; safe to overlay */
    #pragma unroll
    for (int t = 0; t < 16; t++) {
        int c = nb + t * 8 + tig * 2;
        sEV[r0 * 260 + c]           = acc[t][0];
        sEV[r0 * 260 + c + 1]       = acc[t][1];
        sEV[(r0 + 8) * 260 + c]     = acc[t][2];
        sEV[(r0 + 8) * 260 + c + 1] = acc[t][3];
    }
    __syncthreads();

    /* phase C: warp w -> edges e0 + w*8 .. +7, both heads */
    int c0 = lane * 8;
    const float4* ap = (const float4*)(att + c0);
    float4 at0 = ap[0], at1 = ap[1];
    #pragma unroll
    for (int j = 0; j < 8; j++) {
        int le = w * 8 + j;
        int e = e0 + le;
        int ce = (e < N_EDGES) ? e : N_EDGES - 1;
        int src = ei[ce];
        int dst = ei[N_EDGES + ce];
        const float4* xlp = (const float4*)(g_xl + (size_t)src * 256 + c0);
        const float4* xrp = (const float4*)(g_xr + (size_t)dst * 256 + c0);
        const float4* evp = (const float4*)(sEV + le * 260 + c0);
        float4 ev0 = evp[0], ev1 = evp[1];
        float s = 0.f, m;
        {
            float4 a = xlp[0], b = xrp[0];
            m = a.x + b.x + ev0.x; m = (m > 0.f) ? m : 0.2f * m; s += m * at0.x;
            m = a.y + b.y + ev0.y; m = (m > 0.f) ? m : 0.2f * m; s += m * at0.y;
            m = a.z + b.z + ev0.z; m = (m > 0.f) ? m : 0.2f * m; s += m * at0.z;
            m = a.w + b.w + ev0.w; m = (m > 0.f) ? m : 0.2f * m; s += m * at0.w;
        }
        {
            float4 a = xlp[1], b = xrp[1];
            m = a.x + b.x + ev1.x; m = (m > 0.f) ? m : 0.2f * m; s += m * at1.x;
            m = a.y + b.y + ev1.y; m = (m > 0.f) ? m : 0.2f * m; s += m * at1.y;
            m = a.z + b.z + ev1.z; m = (m > 0.f) ? m : 0.2f * m; s += m * at1.z;
            m = a.w + b.w + ev1.w; m = (m > 0.f) ? m : 0.2f * m; s += m * at1.w;
        }
        #pragma unroll
        for (int o = 8; o > 0; o >>= 1) s += __shfl_xor_sync(0xffffffffu, s, o);
        if ((lane & 15) == 0 && e < N_EDGES)
            g_logit[(size_t)e * 2 + (lane >> 4)] = s;
    }
}

/* ------------------------------------------------------------------ */
/* layer-2 logits, fused tf32-mma: block = 64 edges, N=128, overlay    */
/* smem: phase A/B: sW [32][136] @0 17408 | sA [64][36] @17408 9216    */
/*       phase C:   sEV [64][132] @0 33792                             */
/* ------------------------------------------------------------------ */
#define L2_SMEM_BYTES 33792

__global__ void __launch_bounds__(256) k_logit_mma_l2(
        const int* __restrict__ ei, const float* __restrict__ edge_attr,
        const float* __restrict__ We, const float* __restrict__ att) {
    extern __shared__ char smem[];
    uint32_t* sW  = (uint32_t*)(smem);            /* [32][136] tf32 */
    uint32_t* sA  = (uint32_t*)(smem + 17408);    /* [64][36]  tf32 */
    float*    sEV = (float*)(smem);               /* [64][132] fp32 overlay */

    int tid = threadIdx.x;
    int e0 = blockIdx.x * 64;

    #pragma unroll
    for (int t = 0; t < 4; t++) {
        int idx4 = tid + t * 256;
        int k = idx4 >> 5, c4 = idx4 & 31;
        float4 v = *(const float4*)(We + k * 128 + c4 * 4);
        uint4 u = make_uint4(f2tf(v.x), f2tf(v.y), f2tf(v.z), f2tf(v.w));
        *(uint4*)(sW + k * 136 + c4 * 4) = u;
    }
    #pragma unroll
    for (int t = 0; t < 2; t++) {
        int idx4 = tid + t * 256;
        int row = idx4 >> 3, kk4 = idx4 & 7;
        int ge = e0 + row; if (ge >= N_EDGES) ge = N_EDGES - 1;
        float4 v = *(const float4*)(edge_attr + (size_t)ge * 32 + kk4 * 4);
        uint4 u = make_uint4(f2tf(v.x), f2tf(v.y), f2tf(v.z), f2tf(v.w));
        *(uint4*)(sA + row * 36 + kk4 * 4) = u;
    }
    __syncthreads();

    int lane = tid & 31, w = tid >> 5;
    int g = lane >> 2, tig = lane & 3;
    int mt = w & 3, nh = w >> 2;
    int r0 = mt * 16 + g;
    int nb = nh * 64;

    float acc[8][4];
    #pragma unroll
    for (int t = 0; t < 8; t++)
        #pragma unroll
        for (int q = 0; q < 4; q++) acc[t][q] = 0.f;

    #pragma unroll
    for (int ks = 0; ks < 4; ks++) {
        int k0 = ks * 8;
        uint32_t a0 = sA[r0 * 36 + k0 + tig];
        uint32_t a1 = sA[(r0 + 8) * 36 + k0 + tig];
        uint32_t a2 = sA[r0 * 36 + k0 + tig + 4];
        uint32_t a3 = sA[(r0 + 8) * 36 + k0 + tig + 4];
        #pragma unroll
        for (int t = 0; t < 8; t++) {
            uint32_t b0 = sW[(k0 + tig) * 136 + nb + t * 8 + g];
            uint32_t b1 = sW[(k0 + tig + 4) * 136 + nb + t * 8 + g];
            mma_tf32(acc[t], a0, a1, a2, a3, b0, b1);
        }
    }
    __syncthreads();   /* overlay safe point */
    #pragma unroll
    for (int t = 0; t < 8; t++) {
        int c = nb + t * 8 + tig * 2;
        sEV[r0 * 132 + c]           = acc[t][0];
        sEV[r0 * 132 + c + 1]       = acc[t][1];
        sEV[(r0 + 8) * 132 + c]     = acc[t][2];
        sEV[(r0 + 8) * 132 + c + 1] = acc[t][3];
    }
    __syncthreads();

    int c0 = lane * 4;
    float4 at = *(const float4*)(att + c0);
    #pragma unroll
    for (int j = 0; j < 8; j++) {
        int le = w * 8 + j;
        int e = e0 + le;
        int ce = (e < N_EDGES) ? e : N_EDGES - 1;
        int src = ei[ce];
        int dst = ei[N_EDGES + ce];
        float4 a = *(const float4*)(g_xl + (size_t)src * 128 + c0);
        float4 b = *(const float4*)(g_xr + (size_t)dst * 128 + c0);
        float4 ev = *(const float4*)(sEV + le * 132 + c0);
        float s = 0.f, m;
        m = a.x + b.x + ev.x; m = (m > 0.f) ? m : 0.2f * m; s += m * at.x;
        m = a.y + b.y + ev.y; m = (m > 0.f) ? m : 0.2f * m; s += m * at.y;
        m = a.z + b.z + ev.z; m = (m > 0.f) ? m : 0.2f * m; s += m * at.z;
        m = a.w + b.w + ev.w; m = (m > 0.f) ? m : 0.2f * m; s += m * at.w;
        #pragma unroll
        for (int o = 16; o > 0; o >>= 1) s += __shfl_xor_sync(0xffffffffu, s, o);
        if (lane == 0 && e < N_EDGES)
            g_logit[e] = s;
    }
}

/* self-loop logits: warp per node, no lmax */
template <int H>
__global__ void k_logit_self(const float* __restrict__ att,
                             const float* __restrict__ loop_ea) {
    const int HC = H * 128;
    const int CPL = HC / 32;
    int n = (blockIdx.x * blockDim.x + threadIdx.x) >> 5;
    if (n >= N_NODES) return;
    int lane = threadIdx.x & 31;
    int c0 = lane * CPL;
    const float4* xlp = (const float4*)(g_xl + (size_t)n * HC + c0);
    const float4* xrp = (const float4*)(g_xr + (size_t)n * HC + c0);
    const float4* lp  = (const float4*)(loop_ea + c0);
    const float4* ap  = (const float4*)(att + c0);
    float s = 0.f;
    #pragma unroll
    for (int q4 = 0; q4 < CPL / 4; q4++) {
        float4 a = xlp[q4], b = xrp[q4], e = lp[q4], at = ap[q4];
        float m;
        m = a.x + b.x + e.x; m = (m > 0.f) ? m : 0.2f * m; s += m * at.x;
        m = a.y + b.y + e.y; m = (m > 0.f) ? m : 0.2f * m; s += m * at.y;
        m = a.z + b.z + e.z; m = (m > 0.f) ? m : 0.2f * m; s += m * at.z;
        m = a.w + b.w + e.w; m = (m > 0.f) ? m : 0.2f * m; s += m * at.w;
    }
    if (H == 2) {
        #pragma unroll
        for (int o = 8; o > 0; o >>= 1) s += __shfl_xor_sync(0xffffffffu, s, o);
        if ((lane & 15) == 0) {
            int h = lane >> 4;
            g_logit[(size_t)(N_EDGES + n) * 2 + h] = s;
        }
    } else {
        #pragma unroll
        for (int o = 16; o > 0; o >>= 1) s += __shfl_xor_sync(0xffffffffu, s, o);
        if (lane == 0)
            g_logit[N_EDGES + n] = s;
    }
}

/* ------------------------------------------------------------------ */
/* aggregation, fused softmax (no lmax): warp per dst node, CSR        */
/* ------------------------------------------------------------------ */
template <int H>
__global__ void k_agg(const float* __restrict__ bias, float* __restrict__ z) {
    const int HC = H * 128;
    const int CPL = HC / 32;
    int n = (blockIdx.x * blockDim.x + threadIdx.x) >> 5;
    if (n >= N_NODES) return;
    int lane = threadIdx.x & 31;
    int c0 = lane * CPL;
    int h = (H == 2) ? (lane >> 4) : 0;
    float sum_p = 0.f;
    float acc[8];
    #pragma unroll
    for (int q = 0; q < CPL; q++) acc[q] = 0.f;
    int b0 = g_off[n], b1 = g_off[n + 1];
    for (int idx = b0; idx < b1; idx++) {
        int e = g_eidx[idx];
        int src = g_esrc[idx];
        float p = __expf(g_logit[(size_t)e * H + h]);
        sum_p += p;
        const float4* xp = (const float4*)(g_xl + (size_t)src * HC + c0);
        #pragma unroll
        for (int q4 = 0; q4 < CPL / 4; q4++) {
            float4 v = xp[q4];
            acc[q4 * 4 + 0] += p * v.x;
            acc[q4 * 4 + 1] += p * v.y;
            acc[q4 * 4 + 2] += p * v.z;
            acc[q4 * 4 + 3] += p * v.w;
        }
    }
    float inv = 1.f / sum_p;
    #pragma unroll
    for (int q = 0; q < CPL; q++) acc[q] *= inv;
    if (H == 2) {
        #pragma unroll
        for (int q = 0; q < 8; q++)
            acc[q] = 0.5f * (acc[q] + __shfl_xor_sync(0xffffffffu, acc[q], 16));
        if (lane < 16) {
            int c = lane * 8;
            float4 o0, o1;
            float v;
            v = acc[0] + bias[c + 0]; o0.x = (v > 0.f) ? v : expm1f(v);
            v = acc[1] + bias[c + 1]; o0.y = (v > 0.f) ? v : expm1f(v);
            v = acc[2] + bias[c + 2]; o0.z = (v > 0.f) ? v : expm1f(v);
            v = acc[3] + bias[c + 3]; o0.w = (v > 0.f) ? v : expm1f(v);
            v = acc[4] + bias[c + 4]; o1.x = (v > 0.f) ? v : expm1f(v);
            v = acc[5] + bias[c + 5]; o1.y = (v > 0.f) ? v : expm1f(v);
            v = acc[6] + bias[c + 6]; o1.z = (v > 0.f) ? v : expm1f(v);
            v = acc[7] + bias[c + 7]; o1.w = (v > 0.f) ? v : expm1f(v);
            *(float4*)(z + (size_t)n * 128 + c) = o0;
            *(float4*)(z + (size_t)n * 128 + c + 4) = o1;
        }
    } else {
        int c = lane * 4;
        float4 o;
        float v;
        v = acc[0] + bias[c + 0]; o.x = (v > 0.f) ? v : expm1f(v);
        v = acc[1] + bias[c + 1]; o.y = (v > 0.f) ? v : expm1f(v);
        v = acc[2] + bias[c + 2]; o.z = (v > 0.f) ? v : expm1f(v);
        v = acc[3] + bias[c + 3]; o.w = (v > 0.f) ? v : expm1f(v);
        *(float4*)(z + (size_t)n * 128 + c) = o;
    }
}

/* ------------------------------------------------------------------ */
/* fused edge classifier, tf32 tensor cores (R15 version)              */
/* ------------------------------------------------------------------ */
#define CLS_SMEM_BYTES 104448

__global__ void __launch_bounds__(256) k_cls(
        const int* __restrict__ ei, const float* __restrict__ edge_attr,
        const float* __restrict__ Wc1, const float* __restrict__ bc1,
        const float* __restrict__ Wc2, const float* __restrict__ bc2,
        const float* __restrict__ Wc3, const float* __restrict__ bc3,
        float* __restrict__ out) {
    extern __shared__ char smem[];
    int*      s_src = (int*)smem;
    int*      s_dst = (int*)(smem + 512);
    uint32_t* sAu   = (uint32_t*)(smem + 1024);    /* [128][36]  tf32 */
    uint32_t* sBu   = (uint32_t*)(smem + 19456);   /* [32][136]  tf32 */
    uint32_t* sh1u  = (uint32_t*)(smem + 36864);   /* [128][132] tf32 */
    float*    sh2   = (float*)(smem + 1024);       /* [128][68] fp32 overlay */

    int tid = threadIdx.x;
    int e0 = blockIdx.x * 128;
    {
        int ge = e0 + (tid & 127);
        if (ge >= N_EDGES) ge = N_EDGES - 1;
        if (tid < 128) s_src[tid] = ei[ge];
        else           s_dst[tid - 128] = ei[N_EDGES + ge];
    }
    __syncthreads();

    int lane = tid & 31, w = tid >> 5;
    int g = lane >> 2, tig = lane & 3;
    int r0 = w * 16 + g;

    float acc[16][4];
    #pragma unroll
    for (int t = 0; t < 16; t++)
        #pragma unroll
        for (int q = 0; q < 4; q++) acc[t][q] = 0.f;

    for (int kc = 0; kc < 9; kc++) {
        #pragma unroll
        for (int t = 0; t < 4; t++) {
            int idx4 = tid + t * 256;
            int row = idx4 >> 3, kk4 = idx4 & 7;
            int k0 = kc * 32 + kk4 * 4;
            float4 v;
            if (kc < 4)
                v = *(const float4*)(g_h + (size_t)s_src[row] * 128 + k0);
            else if (kc < 8)
                v = *(const float4*)(g_h + (size_t)s_dst[row] * 128 + (k0 - 128));
            else {
                int ge = e0 + row; if (ge >= N_EDGES) ge = N_EDGES - 1;
                v = *(const float4*)(edge_attr + (size_t)ge * 32 + (k0 - 256));
            }
            uint4 u = make_uint4(f2tf(v.x), f2tf(v.y), f2tf(v.z), f2tf(v.w));
            *(uint4*)(sAu + row * 36 + kk4 * 4) = u;
        }
        #pragma unroll
        for (int t = 0; t < 4; t++) {
            int idx4 = tid + t * 256;
            int k = idx4 >> 5, c4 = idx4 & 31;
            float4 v = *(const float4*)(Wc1 + (size_t)(kc * 32 + k) * 128 + c4 * 4);
            uint4 u = make_uint4(f2tf(v.x), f2tf(v.y), f2tf(v.z), f2tf(v.w));
            *(uint4*)(sBu + k * 136 + c4 * 4) = u;
        }
        __syncthreads();
        #pragma unroll
        for (int ks = 0; ks < 4; ks++) {
            int k0 = ks * 8;
            uint32_t a0 = sAu[r0 * 36 + k0 + tig];
            uint32_t a1 = sAu[(r0 + 8) * 36 + k0 + tig];
            uint32_t a2 = sAu[r0 * 36 + k0 + tig + 4];
            uint32_t a3 = sAu[(r0 + 8) * 36 + k0 + tig + 4];
            #pragma unroll
            for (int t = 0; t < 16; t++) {
                uint32_t b0 = sBu[(k0 + tig) * 136 + t * 8 + g];
                uint32_t b1 = sBu[(k0 + tig + 4) * 136 + t * 8 + g];
                mma_tf32(acc[t], a0, a1, a2, a3, b0, b1);
            }
        }
        __syncthreads();
    }
    #pragma unroll
    for (int t = 0; t < 16; t++) {
        int c = t * 8 + tig * 2;
        float bb0 = bc1[c], bb1 = bc1[c + 1];
        sh1u[r0 * 132 + c]           = f2tf(fmaxf(acc[t][0] + bb0, 0.f));
        sh1u[r0 * 132 + c + 1]       = f2tf(fmaxf(acc[t][1] + bb1, 0.f));
        sh1u[(r0 + 8) * 132 + c]     = f2tf(fmaxf(acc[t][2] + bb0, 0.f));
        sh1u[(r0 + 8) * 132 + c + 1] = f2tf(fmaxf(acc[t][3] + bb1, 0.f));
    }
    __syncthreads();

    float acc2[8][4];
    #pragma unroll
    for (int t = 0; t < 8; t++)
        #pragma unroll
        for (int q = 0; q < 4; q++) acc2[t][q] = 0.f;

    for (int kc = 0; kc < 4; kc++) {
        #pragma unroll
        for (int t = 0; t < 2; t++) {
            int idx4 = tid + t * 256;
            int k = idx4 >> 4, c4 = idx4 & 15;
            float4 v = *(const float4*)(Wc2 + (size_t)(kc * 32 + k) * 64 + c4 * 4);
            uint4 u = make_uint4(f2tf(v.x), f2tf(v.y), f2tf(v.z), f2tf(v.w));
            *(uint4*)(sBu + k * 136 + c4 * 4) = u;
        }
        __syncthreads();
        #pragma unroll
        for (int ks = 0; ks < 4; ks++) {
            int kk = kc * 32 + ks * 8;
            uint32_t a0 = sh1u[r0 * 132 + kk + tig];
            uint32_t a1 = sh1u[(r0 + 8) * 132 + kk + tig];
            uint32_t a2 = sh1u[r0 * 132 + kk + tig + 4];
            uint32_t a3 = sh1u[(r0 + 8) * 132 + kk + tig + 4];
            #pragma unroll
            for (int t = 0; t < 8; t++) {
                uint32_t b0 = sBu[(ks * 8 + tig) * 136 + t * 8 + g];
                uint32_t b1 = sBu[(ks * 8 + tig + 4) * 136 + t * 8 + g];
                mma_tf32(acc2[t], a0, a1, a2, a3, b0, b1);
            }
        }
        __syncthreads();
    }
    #pragma unroll
    for (int t = 0; t < 8; t++) {
        int c = t * 8 + tig * 2;
        float bb0 = bc2[c], bb1 = bc2[c + 1];
        sh2[r0 * 68 + c]           = fmaxf(acc2[t][0] + bb0, 0.f);
        sh2[r0 * 68 + c + 1]       = fmaxf(acc2[t][1] + bb1, 0.f);
        sh2[(r0 + 8) * 68 + c]     = fmaxf(acc2[t][2] + bb0, 0.f);
        sh2[(r0 + 8) * 68 + c + 1] = fmaxf(acc2[t][3] + bb1, 0.f);
    }
    __syncthreads();

    {
        int e = tid >> 1;
        int o = tid & 1;
        float s = bc3[o];
        const float* hr = sh2 + e * 68;
        #pragma unroll 8
        for (int k = 0; k < 64; k++) s += hr[k] * Wc3[k * 2 + o];
        int ge = e0 + e;
        if (ge < N_EDGES) out[(size_t)ge * 2 + o] = s;
    }
}

/* ------------------------------------------------------------------ */
/* launch: dual-stream overlap, mma logits, fused GRU                  */
/* ------------------------------------------------------------------ */
extern "C" void kernel_launch(void* const* d_in, const int* in_sizes, int n_in,
                              void* d_out, int out_size) {
    (void)in_sizes; (void)n_in; (void)out_size;
    const float* x     = (const float*)d_in[0];
    const int*   ei    = (const int*)d_in[1];
    const float* ea    = (const float*)d_in[2];
    /* d_in[3] global_ids unused */
    const float* Wl1 = (const float*)d_in[4];
    const float* bl1 = (const float*)d_in[5];
    const float* Wr1 = (const float*)d_in[6];
    const float* br1 = (const float*)d_in[7];
    const float* We1 = (const float*)d_in[8];
    const float* att1 = (const float*)d_in[9];
    const float* bias1 = (const float*)d_in[10];
    const float* Wl2 = (const float*)d_in[11];
    const float* bl2 = (const float*)d_in[12];
    const float* Wr2 = (const float*)d_in[13];
    const float* br2 = (const float*)d_in[14];
    const float* We2 = (const float*)d_in[15];
    const float* att2 = (const float*)d_in[16];
    const float* bias2 = (const float*)d_in[17];
    const float* W_ih = (const float*)d_in[18];
    /* d_in[19] W_hh unused: h_prev == 0 */
    const float* b_ih = (const float*)d_in[20];
    const float* b_hh = (const float*)d_in[21];
    const float* Wc1 = (const float*)d_in[22];
    const float* bc1 = (const float*)d_in[23];
    const float* Wc2 = (const float*)d_in[24];
    const float* bc2 = (const float*)d_in[25];
    const float* Wc3 = (const float*)d_in[26];
    const float* bc3 = (const float*)d_in[27];
    float* out = (float*)d_out;

    float *p_xl, *p_xr, *p_z1, *p_z2, *p_h, *p_lea1, *p_lea2;
    cudaGetSymbolAddress((void**)&p_xl, g_xl);
    cudaGetSymbolAddress((void**)&p_xr, g_xr);
    cudaGetSymbolAddress((void**)&p_z1, g_z1);
    cudaGetSymbolAddress((void**)&p_z2, g_z2);
    cudaGetSymbolAddress((void**)&p_h,  g_h);
    cudaGetSymbolAddress((void**)&p_lea1, g_loop_ea1);
    cudaGetSymbolAddress((void**)&p_lea2, g_loop_ea2);

    /* one-time setup (first call is the uncaptured correctness run) */
    static int setup_done = 0;
    static cudaStream_t s2;
    static cudaEvent_t ev0, evL, evCSR, evAgg1, evX2;
    if (!setup_done) {
        cudaFuncSetAttribute(k_cls, cudaFuncAttributeMaxDynamicSharedMemorySize,
                             CLS_SMEM_BYTES);
        cudaFuncSetAttribute(k_logit_mma_l1, cudaFuncAttributeMaxDynamicSharedMemorySize,
                             L1_SMEM_BYTES);
        cudaFuncSetAttribute(k_logit_mma_l2, cudaFuncAttributeMaxDynamicSharedMemorySize,
                             L2_SMEM_BYTES);
        cudaStreamCreateWithFlags(&s2, cudaStreamNonBlocking);
        cudaEventCreateWithFlags(&ev0,   cudaEventDisableTiming);
        cudaEventCreateWithFlags(&evL,   cudaEventDisableTiming);
        cudaEventCreateWithFlags(&evCSR, cudaEventDisableTiming);
        cudaEventCreateWithFlags(&evAgg1, cudaEventDisableTiming);
        cudaEventCreateWithFlags(&evX2,  cudaEventDisableTiming);
        setup_done = 1;
    }

    dim3 tb(256);
    int gy = (N_NODES + 127) / 128;
    int gy64 = (N_NODES + 63) / 64;
    int logit_blocks = (N_EDGES + 63) / 64;

    /* main: init, then the layer-1 GEMM+logit chain (logit_mma_l1 = 4th launch) */
    k_init<<<(N_NODES + 255) / 256, 256>>>();
    cudaEventRecord(ev0, 0);
    k_gemm<<<dim3(2, gy), tb>>>(x, Wl1, bl1, p_xl, N_NODES, 256);
    k_gemm<<<dim3(2, gy), tb>>>(x, Wr1, br1, p_xr, N_NODES, 256);
    k_logit_mma_l1<<<logit_blocks, 256, L1_SMEM_BYTES>>>(ei, ea, We1, att1);

    /* side stream: easum/loopea + CSR build, forked after k_init */
    cudaStreamWaitEvent(s2, ev0, 0);
    k_easum<<<(N_EDGES + 1023) / 1024, 256, 0, s2>>>(ea);
    k_loopea<<<1, 256, 0, s2>>>(We1, We2);
    cudaEventRecord(evL, s2);
    k_deg<<<(EF + 255) / 256, 256, 0, s2>>>(ei);
    k_blocksum<<<NB_SCAN, 256, 0, s2>>>();
    k_scanb<<<1, 256, 0, s2>>>();
    k_scanfinal<<<NB_SCAN, 256, 0, s2>>>();
    k_scatter<<<(EF + 255) / 256, 256, 0, s2>>>(ei);
    cudaEventRecord(evCSR, s2);

    /* main: self-loop logits need loopea; agg needs CSR */
    cudaStreamWaitEvent(0, evL, 0);
    k_logit_self<2><<<(N_NODES + 7) / 8, 256>>>(att1, p_lea1);
    cudaStreamWaitEvent(0, evCSR, 0);
    k_agg<2><<<(N_NODES + 7) / 8, 256>>>(bias1, p_z1);
    cudaEventRecord(evAgg1, 0);

    /* layer 2: xl2 on main, xr2 concurrent on s2 */
    cudaStreamWaitEvent(s2, evAgg1, 0);
    k_gemm<<<dim3(1, gy), tb, 0, s2>>>(p_z1, Wr2, br2, p_xr, N_NODES, 128);
    cudaEventRecord(evX2, s2);
    k_gemm<<<dim3(1, gy), tb>>>(p_z1, Wl2, bl2, p_xl, N_NODES, 128);
    cudaStreamWaitEvent(0, evX2, 0);
    k_logit_mma_l2<<<logit_blocks, 256, L2_SMEM_BYTES>>>(ei, ea, We2, att2);
    k_logit_self<1><<<(N_NODES + 7) / 8, 256>>>(att2, p_lea2);
    k_agg<1><<<(N_NODES + 7) / 8, 256>>>(bias2, p_z2);

    /* fused GRU GEMM (h_prev = 0): writes g_h directly */
    k_gru_gemm<<<dim3(2, gy64), tb>>>(p_z2, W_ih, b_ih, b_hh, p_h, N_NODES);

    /* edge classifier (tf32 tensor cores) */
    k_cls<<<(N_EDGES + 127) / 128, 256, CLS_SMEM_BYTES>>>(
        ei, ea, Wc1, bc1, Wc2, bc2, Wc3, bc3, out);
}